// round 12
// baseline (speedup 1.0000x reference)
#include <cuda_runtime.h>
#include <cuda_fp16.h>
#include <math.h>
#include <stdint.h>

#define DM     1024
#define HEADS  16
#define DKH    64
#define BATCH  2
#define SEQ    2048
#define MROWS  (BATCH*SEQ)   // 4096

// Scratch (device globals; allocation-free per harness rules)
__device__ __half g_q[HEADS*BATCH*SEQ*DKH];    // head-layout projections
__device__ __half g_k[HEADS*BATCH*SEQ*DKH];
__device__ __half g_v[HEADS*BATCH*SEQ*DKH];
__device__ __half g_ctx[(size_t)MROWS*DM];     // attention output (concat)
__device__ __half g_xq[(size_t)MROWS*DM];      // fp16 copies of inputs
__device__ __half g_xk[(size_t)MROWS*DM];
__device__ __half g_xv[(size_t)MROWS*DM];
__device__ __half g_wq[(size_t)DM*DM];         // fp16 weights
__device__ __half g_wo[(size_t)DM*DM];

// ---- helpers --------------------------------------------------------------
__device__ __forceinline__ unsigned pack_h2(float a, float b) {
    __half2 h = __floats2half2_rn(a, b);
    return *reinterpret_cast<unsigned*>(&h);
}
__device__ __forceinline__ uint2 cvt_f4h(float4 v) {
    uint2 r; r.x = pack_h2(v.x, v.y); r.y = pack_h2(v.z, v.w); return r;
}
__device__ __forceinline__ void mma_f16(float d[4], const unsigned a[4],
                                        unsigned b0, unsigned b1) {
    asm("mma.sync.aligned.m16n8k16.row.col.f32.f16.f16.f32 "
        "{%0,%1,%2,%3}, {%4,%5,%6,%7}, {%8,%9}, {%0,%1,%2,%3};"
        : "+f"(d[0]), "+f"(d[1]), "+f"(d[2]), "+f"(d[3])
        : "r"(a[0]), "r"(a[1]), "r"(a[2]), "r"(a[3]), "r"(b0), "r"(b1));
}
__device__ __forceinline__ void ldsm_x4(unsigned r[4], unsigned saddr) {
    asm volatile("ldmatrix.sync.aligned.m8n8.x4.shared.b16 {%0,%1,%2,%3}, [%4];"
                 : "=r"(r[0]), "=r"(r[1]), "=r"(r[2]), "=r"(r[3])
                 : "r"(saddr));
}
__device__ __forceinline__ void ldsm_x4t(unsigned r[4], unsigned saddr) {
    asm volatile("ldmatrix.sync.aligned.m8n8.x4.trans.shared.b16 {%0,%1,%2,%3}, [%4];"
                 : "=r"(r[0]), "=r"(r[1]), "=r"(r[2]), "=r"(r[3])
                 : "r"(saddr));
}
__device__ __forceinline__ void cp16(unsigned dst, const void* src) {
    asm volatile("cp.async.ca.shared.global [%0], [%1], 16;"
                 :: "r"(dst), "l"(src));
}
__device__ __forceinline__ void cp_commit() {
    asm volatile("cp.async.commit_group;" ::: "memory");
}
template<int N>
__device__ __forceinline__ void cp_wait() {
    asm volatile("cp.async.wait_group %0;" :: "n"(N) : "memory");
}

// ---------------------------------------------------------------------------
// f32 -> f16 conversion: z selects {query,key,value,Wq,Wo}
// ---------------------------------------------------------------------------
__global__ void cvt_kernel(const float* __restrict__ q,
                           const float* __restrict__ k,
                           const float* __restrict__ v,
                           const float* __restrict__ wq,
                           const float* __restrict__ wo)
{
    const int z = blockIdx.z;
    const float* src; __half* dst; int nf4;
    if      (z == 0) { src = q;  dst = g_xq; nf4 = MROWS * DM / 4; }
    else if (z == 1) { src = k;  dst = g_xk; nf4 = MROWS * DM / 4; }
    else if (z == 2) { src = v;  dst = g_xv; nf4 = MROWS * DM / 4; }
    else if (z == 3) { src = wq; dst = g_wq; nf4 = DM * DM / 4; }
    else             { src = wo; dst = g_wo; nf4 = DM * DM / 4; }
    for (int i = blockIdx.x * blockDim.x + threadIdx.x; i < nf4;
         i += gridDim.x * blockDim.x) {
        float4 v4 = ((const float4*)src)[i];
        ((uint2*)dst)[i] = cvt_f4h(v4);
    }
}

// ---------------------------------------------------------------------------
// fp16 GEMM, 3-stage cp.async pipeline, K-STAGE 64 (halved barrier count):
// C[M,1024] = A @ W + bias.  CTA 128x128, 8 warps (2m x 4n), warp tile 64x32.
// A smem [128][72] halfs, B smem [64][136] halfs; stage 35KB x3 = 105KB,
// 2 CTAs/SM.  64 back-to-back mma per warp per stage.
// MODE 0: A = g_x{q,k,v} (z), B = g_wq; -> head layout (__half), q scaled.
// MODE 1: A = g_ctx, B = g_wo; -> f32 out + bias.
// ---------------------------------------------------------------------------
#define KSTG 64
#define GA_STR 72
#define GB_STR 136
#define GA_HALFS (128 * GA_STR)            // 9216
#define GB_HALFS (KSTG * GB_STR)           // 8704
#define G_STAGE  (GA_HALFS + GB_HALFS)     // 17920 halfs
#define GEMM_SMEM (3 * G_STAGE * 2)        // 107520 bytes
#define NIT (DM / KSTG)                    // 16

__device__ __forceinline__ void gemm_stage(const __half* __restrict__ A,
                                           const __half* __restrict__ W,
                                           unsigned smBase, int buf, int kt,
                                           int tid)
{
    const unsigned aB = smBase + (unsigned)buf * (G_STAGE * 2);
    const unsigned bB = aB + GA_HALFS * 2;
#pragma unroll
    for (int l = 0; l < 4; l++) {     // A: 128 rows x 64 halfs = 1024 chunks
        int c = tid + l * 256;
        int row = c >> 3, c16 = c & 7;
        cp16(aB + (row * GA_STR + c16 * 8) * 2,
             A + (size_t)row * DM + kt + c16 * 8);
    }
#pragma unroll
    for (int l = 0; l < 4; l++) {     // B: 64 rows x 128 halfs = 1024 chunks
        int c = tid + l * 256;
        int row = c >> 4, c16 = c & 15;
        cp16(bB + (row * GB_STR + c16 * 8) * 2,
             W + (size_t)(kt + row) * DM + c16 * 8);
    }
}

template<int MODE>
__global__ __launch_bounds__(256, 2)
void gemm_kernel(const float* __restrict__ bias, float* __restrict__ Cout)
{
    extern __shared__ __half smh[];
    const unsigned smBase = (unsigned)__cvta_generic_to_shared(smh);

    const int tid  = threadIdx.x;
    const int warp = tid >> 5, lane = tid & 31;
    const int wm = warp >> 2, wn = warp & 3;
    const int grp = lane >> 2, qi = lane & 3;

    const int z = (MODE == 0) ? blockIdx.z : 0;
    const int gm0 = blockIdx.y * 128;
    const int gn0 = blockIdx.x * 128;

    const __half* __restrict__ A =
        ((MODE == 1) ? g_ctx : (z == 0 ? g_xq : (z == 1 ? g_xk : g_xv)))
        + (size_t)gm0 * DM;
    const __half* __restrict__ W =
        ((MODE == 0) ? g_wq : g_wo) + gn0;

    // ldmatrix lane bases (byte offsets within a stage)
    const unsigned aOff =
        (((wm * 64 + (lane & 7) + ((lane >> 3) & 1) * 8) * GA_STR)
         + (lane >> 4) * 8) * 2;
    const unsigned bOff = GA_HALFS * 2 +
        ((((lane >> 3) * 8 + (lane & 7)) * GB_STR) + wn * 32) * 2;

    float d[4][4][4];
#pragma unroll
    for (int mi = 0; mi < 4; mi++)
#pragma unroll
        for (int ni = 0; ni < 4; ni++)
#pragma unroll
            for (int r = 0; r < 4; r++) d[mi][ni][r] = 0.f;

    // prologue: stages 0, 1
    gemm_stage(A, W, smBase, 0, 0, tid);    cp_commit();
    gemm_stage(A, W, smBase, 1, KSTG, tid); cp_commit();
    cp_wait<1>();
    __syncthreads();

    for (int it = 0; it < NIT; it++) {
        const int buf = it % 3;
        if (it < NIT - 2)
            gemm_stage(A, W, smBase, (it + 2) % 3, (it + 2) * KSTG, tid);
        cp_commit();

        const unsigned sB = smBase + (unsigned)buf * (G_STAGE * 2);
#pragma unroll
        for (int kq = 0; kq < 2; kq++) {          // two k32 chunks
            unsigned bf[4][4];
#pragma unroll
            for (int ni = 0; ni < 4; ni++)
                ldsm_x4t(bf[ni], sB + bOff + kq * (32 * GB_STR * 2) + ni * 16);
#pragma unroll
            for (int kp = 0; kp < 2; kp++) {      // two k16 steps
                unsigned af[4][4];
#pragma unroll
                for (int mi = 0; mi < 4; mi++)
                    ldsm_x4(af[mi], sB + aOff + mi * 16 * (GA_STR * 2)
                                     + (kq * 32 + kp * 16) * 2);
#pragma unroll
                for (int mi = 0; mi < 4; mi++)
#pragma unroll
                    for (int ni = 0; ni < 4; ni++)
                        mma_f16(d[mi][ni], af[mi],
                                bf[ni][kp * 2], bf[ni][kp * 2 + 1]);
            }
        }

        cp_wait<1>();
        __syncthreads();
    }

    // ---- epilogue
    const float qsc = (MODE == 0 && z == 0) ? rsqrtf((float)SEQ) : 1.0f;
#pragma unroll
    for (int ni = 0; ni < 4; ni++) {
        const int gcol = gn0 + wn * 32 + ni * 8 + qi * 2;
        const float b0 = bias[gcol], b1 = bias[gcol + 1];
#pragma unroll
        for (int mi = 0; mi < 4; mi++) {
            const int gr = gm0 + wm * 64 + mi * 16 + grp;
#pragma unroll
            for (int hh = 0; hh < 2; hh++) {
                const int gm = gr + hh * 8;
                float v0 = d[mi][ni][hh * 2 + 0] + b0;
                float v1 = d[mi][ni][hh * 2 + 1] + b1;
                if (MODE == 0) {
                    v0 *= qsc; v1 *= qsc;
                    __half* out = (z == 0) ? g_q : (z == 1) ? g_k : g_v;
                    const int h = gcol >> 6, dd = gcol & 63;
                    const int b = gm >> 11, s = gm & (SEQ - 1);
                    *(unsigned*)&out[(((size_t)h * BATCH + b) * SEQ + s) * DKH + dd]
                        = pack_h2(v0, v1);
                } else {
                    *(float2*)&Cout[(size_t)gm * DM + gcol] = make_float2(v0, v1);
                }
            }
        }
    }
}

// ---------------------------------------------------------------------------
// fp16 flash attention per (h,b) (unchanged from R9): BQ=256, 8 warps x 32
// q-rows; Q in registers; K/V via 3-stage cp.async; lane-local P packing.
// ---------------------------------------------------------------------------
#define KV_STR 72
#define KV_HALFS (64 * KV_STR)              // 4608 halfs (one K or V tile)
#define AT_STAGE (2 * KV_HALFS)             // 9216 halfs per stage
#define ATT_SMEM_BYTES (3 * AT_STAGE * 2)   // 55296 bytes

__device__ __forceinline__ void attn_stage(const __half* __restrict__ K,
                                           const __half* __restrict__ V,
                                           unsigned smBase, int buf,
                                           size_t kb, int tid)
{
    const unsigned base = smBase + (unsigned)buf * (AT_STAGE * 2);
#pragma unroll
    for (int l = 0; l < 2; l++) {
        int c = tid + l * 256;
        int row = c >> 3, c16 = c & 7;
        cp16(base + (row * KV_STR + c16 * 8) * 2,
             K + (kb + row) * DKH + c16 * 8);
    }
#pragma unroll
    for (int l = 0; l < 2; l++) {
        int c = tid + l * 256;
        int row = c >> 3, c16 = c & 7;
        cp16(base + KV_HALFS * 2 + (row * KV_STR + c16 * 8) * 2,
             V + (kb + row) * DKH + c16 * 8);
    }
}

__global__ __launch_bounds__(256)
void attn_kernel()
{
    extern __shared__ __half smh[];
    const unsigned smBase = (unsigned)__cvta_generic_to_shared(smh);

    const int tid  = threadIdx.x;
    const int warp = tid >> 5, lane = tid & 31;
    const int grp  = lane >> 2, qi = lane & 3;
    const int hb   = blockIdx.y;
    const int q0   = blockIdx.x * 256;

    const __half* __restrict__ Q = g_q + (size_t)hb * SEQ * DKH;
    const __half* __restrict__ K = g_k + (size_t)hb * SEQ * DKH;
    const __half* __restrict__ V = g_v + (size_t)hb * SEQ * DKH;

    const int row0 = warp * 32;
    const int rowL = tid >> 3, c8 = tid & 7;

    // ---- stage Q into (aliased) smem, ldmatrix to regs, then release smem
#pragma unroll
    for (int l = 0; l < 8; l++) {
        const int r = rowL + l * 32;
        uint4 v = *(const uint4*)&Q[(size_t)(q0 + r) * DKH + c8 * 8];
        *(uint4*)&smh[r * KV_STR + c8 * 8] = v;
    }
    __syncthreads();

    unsigned qf[2][4][4];
    {
        const unsigned qLane = smBase +
            (((row0 + (lane & 7) + ((lane >> 3) & 1) * 8) * KV_STR)
             + (lane >> 4) * 8) * 2;
#pragma unroll
        for (int m = 0; m < 2; m++)
#pragma unroll
            for (int kp = 0; kp < 4; kp++)
                ldsm_x4(qf[m][kp], qLane + m * 16 * (KV_STR * 2) + kp * 32);
    }
    __syncthreads();

    const unsigned kOff = (((lane & 7) * KV_STR) + (lane >> 3) * 8) * 2;
    const unsigned vOff = KV_HALFS * 2 +
        (((lane >> 3) * 8 + (lane & 7)) * KV_STR) * 2;

    float o[2][8][4];
    float rs[2][2];
#pragma unroll
    for (int m = 0; m < 2; m++) {
        rs[m][0] = 0.f; rs[m][1] = 0.f;
#pragma unroll
        for (int ni = 0; ni < 8; ni++)
#pragma unroll
            for (int r = 0; r < 4; r++) o[m][ni][r] = 0.f;
    }

    attn_stage(K, V, smBase, 0, 0, tid);  cp_commit();
    attn_stage(K, V, smBase, 1, 64, tid); cp_commit();
    cp_wait<1>();
    __syncthreads();

    for (int it = 0; it < 32; it++) {
        const int buf = it % 3;
        if (it < 30)
            attn_stage(K, V, smBase, (it + 2) % 3, (size_t)(it + 2) * 64, tid);
        cp_commit();

        const unsigned sB = smBase + (unsigned)buf * (AT_STAGE * 2);

        float s[2][8][4];
#pragma unroll
        for (int m = 0; m < 2; m++)
#pragma unroll
            for (int ni = 0; ni < 8; ni++)
#pragma unroll
                for (int r = 0; r < 4; r++) s[m][ni][r] = 0.f;

#pragma unroll
        for (int kq = 0; kq < 2; kq++) {
#pragma unroll
            for (int ni = 0; ni < 8; ni++) {
                unsigned kf[4];
                ldsm_x4(kf, sB + kOff + (ni * 8 * KV_STR) * 2 + kq * 64);
#pragma unroll
                for (int m = 0; m < 2; m++) {
                    mma_f16(s[m][ni], qf[m][2 * kq],     kf[0], kf[1]);
                    mma_f16(s[m][ni], qf[m][2 * kq + 1], kf[2], kf[3]);
                }
            }
        }

        unsigned ps[2][4][4];
#pragma unroll
        for (int m = 0; m < 2; m++)
#pragma unroll
            for (int tp = 0; tp < 4; tp++) {
                const float* sa = s[m][2 * tp];
                const float* sb = s[m][2 * tp + 1];
                float e0 = __expf(sa[0]), e1 = __expf(sa[1]);
                float e2 = __expf(sa[2]), e3 = __expf(sa[3]);
                float f0 = __expf(sb[0]), f1 = __expf(sb[1]);
                float f2 = __expf(sb[2]), f3 = __expf(sb[3]);
                rs[m][0] += (e0 + e1) + (f0 + f1);
                rs[m][1] += (e2 + e3) + (f2 + f3);
                ps[m][tp][0] = pack_h2(e0, e1);
                ps[m][tp][1] = pack_h2(e2, e3);
                ps[m][tp][2] = pack_h2(f0, f1);
                ps[m][tp][3] = pack_h2(f2, f3);
            }

#pragma unroll
        for (int tq = 0; tq < 2; tq++) {
#pragma unroll
            for (int ni = 0; ni < 8; ni++) {
                unsigned vf[4];
                ldsm_x4t(vf, sB + vOff + (tq * 32 * KV_STR) * 2 + ni * 16);
#pragma unroll
                for (int m = 0; m < 2; m++) {
                    mma_f16(o[m][ni], ps[m][2 * tq],     vf[0], vf[1]);
                    mma_f16(o[m][ni], ps[m][2 * tq + 1], vf[2], vf[3]);
                }
            }
        }

        cp_wait<1>();
        __syncthreads();
    }

#pragma unroll
    for (int m = 0; m < 2; m++)
#pragma unroll
        for (int j = 0; j < 2; j++) {
            float r = rs[m][j];
            r += __shfl_xor_sync(0xffffffffu, r, 1);
            r += __shfl_xor_sync(0xffffffffu, r, 2);
            rs[m][j] = 1.f / r;
        }

    const int h = hb >> 1, b = hb & 1;
#pragma unroll
    for (int m = 0; m < 2; m++) {
        const int sr0 = q0 + row0 + m * 16 + grp;
#pragma unroll
        for (int ni = 0; ni < 8; ni++) {
            const int col = h * DKH + ni * 8 + qi * 2;
            *(unsigned*)&g_ctx[((size_t)(b * SEQ + sr0)) * DM + col] =
                pack_h2(o[m][ni][0] * rs[m][0], o[m][ni][1] * rs[m][0]);
            *(unsigned*)&g_ctx[((size_t)(b * SEQ + sr0 + 8)) * DM + col] =
                pack_h2(o[m][ni][2] * rs[m][1], o[m][ni][3] * rs[m][1]);
        }
    }
}

// ---------------------------------------------------------------------------
extern "C" void kernel_launch(void* const* d_in, const int* in_sizes, int n_in,
                              void* d_out, int out_size)
{
    (void)in_sizes; (void)n_in; (void)out_size;
    const float* query = (const float*)d_in[0];
    const float* key   = (const float*)d_in[1];
    const float* value = (const float*)d_in[2];
    const float* Wq    = (const float*)d_in[3];
    const float* bq    = (const float*)d_in[4];
    const float* Wo    = (const float*)d_in[5];
    const float* bo    = (const float*)d_in[6];
    float* out = (float*)d_out;

    cudaFuncSetAttribute(gemm_kernel<0>,
                         cudaFuncAttributeMaxDynamicSharedMemorySize, GEMM_SMEM);
    cudaFuncSetAttribute(gemm_kernel<1>,
                         cudaFuncAttributeMaxDynamicSharedMemorySize, GEMM_SMEM);
    cudaFuncSetAttribute(attn_kernel,
                         cudaFuncAttributeMaxDynamicSharedMemorySize,
                         ATT_SMEM_BYTES);

    dim3 blk(256);
    cvt_kernel<<<dim3(1024, 1, 5), blk>>>(query, key, value, Wq, Wo);
    gemm_kernel<0><<<dim3(DM / 128, MROWS / 128, 3), blk, GEMM_SMEM>>>(bq, nullptr);
    attn_kernel<<<dim3(SEQ / 256, HEADS * BATCH), blk, ATT_SMEM_BYTES>>>();
    gemm_kernel<1><<<dim3(DM / 128, MROWS / 128, 1), blk, GEMM_SMEM>>>(bo, out);
}

// round 13
// speedup vs baseline: 1.0368x; 1.0368x over previous
#include <cuda_runtime.h>
#include <cuda_fp16.h>
#include <math.h>
#include <stdint.h>

#define DM     1024
#define HEADS  16
#define DKH    64
#define BATCH  2
#define SEQ    2048
#define MROWS  (BATCH*SEQ)   // 4096

// Scratch (device globals; allocation-free per harness rules)
__device__ __half g_q[HEADS*BATCH*SEQ*DKH];    // head-layout projections
__device__ __half g_k[HEADS*BATCH*SEQ*DKH];
__device__ __half g_v[HEADS*BATCH*SEQ*DKH];
__device__ __half g_ctx[(size_t)MROWS*DM];     // attention output (concat)
__device__ __half g_xq[(size_t)MROWS*DM];      // fp16 copies of inputs
__device__ __half g_xk[(size_t)MROWS*DM];
__device__ __half g_xv[(size_t)MROWS*DM];
__device__ __half g_wq[(size_t)DM*DM];         // fp16 weights
__device__ __half g_wo[(size_t)DM*DM];

// ---- helpers --------------------------------------------------------------
__device__ __forceinline__ unsigned pack_h2(float a, float b) {
    __half2 h = __floats2half2_rn(a, b);
    return *reinterpret_cast<unsigned*>(&h);
}
__device__ __forceinline__ uint2 cvt_f4h(float4 v) {
    uint2 r; r.x = pack_h2(v.x, v.y); r.y = pack_h2(v.z, v.w); return r;
}
__device__ __forceinline__ void mma_f16(float d[4], const unsigned a[4],
                                        unsigned b0, unsigned b1) {
    asm("mma.sync.aligned.m16n8k16.row.col.f32.f16.f16.f32 "
        "{%0,%1,%2,%3}, {%4,%5,%6,%7}, {%8,%9}, {%0,%1,%2,%3};"
        : "+f"(d[0]), "+f"(d[1]), "+f"(d[2]), "+f"(d[3])
        : "r"(a[0]), "r"(a[1]), "r"(a[2]), "r"(a[3]), "r"(b0), "r"(b1));
}
__device__ __forceinline__ void ldsm_x4(unsigned r[4], unsigned saddr) {
    asm volatile("ldmatrix.sync.aligned.m8n8.x4.shared.b16 {%0,%1,%2,%3}, [%4];"
                 : "=r"(r[0]), "=r"(r[1]), "=r"(r[2]), "=r"(r[3])
                 : "r"(saddr));
}
__device__ __forceinline__ void ldsm_x4t(unsigned r[4], unsigned saddr) {
    asm volatile("ldmatrix.sync.aligned.m8n8.x4.trans.shared.b16 {%0,%1,%2,%3}, [%4];"
                 : "=r"(r[0]), "=r"(r[1]), "=r"(r[2]), "=r"(r[3])
                 : "r"(saddr));
}
__device__ __forceinline__ void cp16(unsigned dst, const void* src) {
    asm volatile("cp.async.cg.shared.global [%0], [%1], 16;"
                 :: "r"(dst), "l"(src));
}
__device__ __forceinline__ void cp_commit() {
    asm volatile("cp.async.commit_group;" ::: "memory");
}
template<int N>
__device__ __forceinline__ void cp_wait() {
    asm volatile("cp.async.wait_group %0;" :: "n"(N) : "memory");
}

// ---------------------------------------------------------------------------
// f32 -> f16 conversion: z selects {query,key,value,Wq,Wo}
// ---------------------------------------------------------------------------
__global__ void cvt_kernel(const float* __restrict__ q,
                           const float* __restrict__ k,
                           const float* __restrict__ v,
                           const float* __restrict__ wq,
                           const float* __restrict__ wo)
{
    const int z = blockIdx.z;
    const float* src; __half* dst; int nf4;
    if      (z == 0) { src = q;  dst = g_xq; nf4 = MROWS * DM / 4; }
    else if (z == 1) { src = k;  dst = g_xk; nf4 = MROWS * DM / 4; }
    else if (z == 2) { src = v;  dst = g_xv; nf4 = MROWS * DM / 4; }
    else if (z == 3) { src = wq; dst = g_wq; nf4 = DM * DM / 4; }
    else             { src = wo; dst = g_wo; nf4 = DM * DM / 4; }
    for (int i = blockIdx.x * blockDim.x + threadIdx.x; i < nf4;
         i += gridDim.x * blockDim.x) {
        float4 v4 = ((const float4*)src)[i];
        ((uint2*)dst)[i] = cvt_f4h(v4);
    }
}

// ---------------------------------------------------------------------------
// fp16 GEMM, 4-stage cp.async pipeline (k-stage 32, wait_group<2>):
// C[M,1024] = A @ W + bias.  CTA 128x128, 8 warps (2m x 4n), warp tile 64x32.
// A smem [128][40] halfs, B smem [32][136] halfs; stage 18.9KB x4 = 75.8KB.
// MODE 0: A = g_x{q,k,v} (z), B = g_wq; -> head layout (__half), q scaled.
// MODE 1: A = g_ctx, B = g_wo; -> f32 out + bias.
// ---------------------------------------------------------------------------
#define GA_STR 40
#define GB_STR 136
#define GA_HALFS (128 * GA_STR)            // 5120
#define GB_HALFS (32 * GB_STR)             // 4352
#define G_STAGE  (GA_HALFS + GB_HALFS)     // 9472 halfs
#define GEMM_SMEM (4 * G_STAGE * 2)        // 75776 bytes

__device__ __forceinline__ void gemm_stage(const __half* __restrict__ A,
                                           const __half* __restrict__ W,
                                           unsigned smBase, int buf, int kt,
                                           int tid)
{
    const unsigned aB = smBase + (unsigned)buf * (G_STAGE * 2);
    const unsigned bB = aB + GA_HALFS * 2;
#pragma unroll
    for (int l = 0; l < 2; l++) {          // A: 128 rows x 32 halfs = 512 chunks
        int c = tid + l * 256;
        int row = c >> 2, c16 = c & 3;
        cp16(aB + (row * GA_STR + c16 * 8) * 2,
             A + (size_t)row * DM + kt + c16 * 8);
    }
#pragma unroll
    for (int l = 0; l < 2; l++) {          // B: 32 rows x 128 halfs = 512 chunks
        int c = tid + l * 256;
        int row = c >> 4, c16 = c & 15;
        cp16(bB + (row * GB_STR + c16 * 8) * 2,
             W + (size_t)(kt + row) * DM + c16 * 8);
    }
}

template<int MODE>
__global__ __launch_bounds__(256, 2)
void gemm_kernel(const float* __restrict__ bias, float* __restrict__ Cout)
{
    extern __shared__ __half smh[];
    const unsigned smBase = (unsigned)__cvta_generic_to_shared(smh);

    const int tid  = threadIdx.x;
    const int warp = tid >> 5, lane = tid & 31;
    const int wm = warp >> 2, wn = warp & 3;
    const int grp = lane >> 2, qi = lane & 3;

    const int z = (MODE == 0) ? blockIdx.z : 0;
    const int gm0 = blockIdx.y * 128;
    const int gn0 = blockIdx.x * 128;

    const __half* __restrict__ A =
        ((MODE == 1) ? g_ctx : (z == 0 ? g_xq : (z == 1 ? g_xk : g_xv)))
        + (size_t)gm0 * DM;
    const __half* __restrict__ W =
        ((MODE == 0) ? g_wq : g_wo) + gn0;

    // ldmatrix lane bases (byte offsets within a stage)
    const unsigned aOff =
        (((wm * 64 + (lane & 7) + ((lane >> 3) & 1) * 8) * GA_STR)
         + (lane >> 4) * 8) * 2;
    const unsigned bOff = GA_HALFS * 2 +
        ((((lane >> 3) * 8 + (lane & 7)) * GB_STR) + wn * 32) * 2;

    float d[4][4][4];
#pragma unroll
    for (int mi = 0; mi < 4; mi++)
#pragma unroll
        for (int ni = 0; ni < 4; ni++)
#pragma unroll
            for (int r = 0; r < 4; r++) d[mi][ni][r] = 0.f;

    // prologue: stages 0, 1, 2
    gemm_stage(A, W, smBase, 0, 0,  tid); cp_commit();
    gemm_stage(A, W, smBase, 1, 32, tid); cp_commit();
    gemm_stage(A, W, smBase, 2, 64, tid); cp_commit();
    cp_wait<2>();
    __syncthreads();

    for (int it = 0; it < 32; it++) {
        const int buf = it & 3;
        if (it < 29)
            gemm_stage(A, W, smBase, (it + 3) & 3, (it + 3) * 32, tid);
        cp_commit();

        const unsigned sB = smBase + (unsigned)buf * (G_STAGE * 2);
        unsigned bf[4][4];
#pragma unroll
        for (int ni = 0; ni < 4; ni++)
            ldsm_x4t(bf[ni], sB + bOff + ni * 16);
#pragma unroll
        for (int kp = 0; kp < 2; kp++) {
            unsigned af[4][4];
#pragma unroll
            for (int mi = 0; mi < 4; mi++)
                ldsm_x4(af[mi], sB + aOff + mi * 16 * (GA_STR * 2) + kp * 32);
#pragma unroll
            for (int mi = 0; mi < 4; mi++)
#pragma unroll
                for (int ni = 0; ni < 4; ni++)
                    mma_f16(d[mi][ni], af[mi], bf[ni][kp * 2], bf[ni][kp * 2 + 1]);
        }

        cp_wait<2>();
        __syncthreads();
    }

    // ---- epilogue
    const float qsc = (MODE == 0 && z == 0) ? rsqrtf((float)SEQ) : 1.0f;
#pragma unroll
    for (int ni = 0; ni < 4; ni++) {
        const int gcol = gn0 + wn * 32 + ni * 8 + qi * 2;
        const float b0 = bias[gcol], b1 = bias[gcol + 1];
#pragma unroll
        for (int mi = 0; mi < 4; mi++) {
            const int gr = gm0 + wm * 64 + mi * 16 + grp;
#pragma unroll
            for (int hh = 0; hh < 2; hh++) {
                const int gm = gr + hh * 8;
                float v0 = d[mi][ni][hh * 2 + 0] + b0;
                float v1 = d[mi][ni][hh * 2 + 1] + b1;
                if (MODE == 0) {
                    v0 *= qsc; v1 *= qsc;
                    __half* out = (z == 0) ? g_q : (z == 1) ? g_k : g_v;
                    const int h = gcol >> 6, dd = gcol & 63;
                    const int b = gm >> 11, s = gm & (SEQ - 1);
                    *(unsigned*)&out[(((size_t)h * BATCH + b) * SEQ + s) * DKH + dd]
                        = pack_h2(v0, v1);
                } else {
                    *(float2*)&Cout[(size_t)gm * DM + gcol] = make_float2(v0, v1);
                }
            }
        }
    }
}

// ---------------------------------------------------------------------------
// fp16 flash attention per (h,b) (unchanged from R9): BQ=256, 8 warps x 32
// q-rows; Q in registers; K/V via 3-stage cp.async; lane-local P packing.
// ---------------------------------------------------------------------------
#define KV_STR 72
#define KV_HALFS (64 * KV_STR)              // 4608 halfs (one K or V tile)
#define AT_STAGE (2 * KV_HALFS)             // 9216 halfs per stage
#define ATT_SMEM_BYTES (3 * AT_STAGE * 2)   // 55296 bytes

__device__ __forceinline__ void attn_stage(const __half* __restrict__ K,
                                           const __half* __restrict__ V,
                                           unsigned smBase, int buf,
                                           size_t kb, int tid)
{
    const unsigned base = smBase + (unsigned)buf * (AT_STAGE * 2);
#pragma unroll
    for (int l = 0; l < 2; l++) {
        int c = tid + l * 256;
        int row = c >> 3, c16 = c & 7;
        cp16(base + (row * KV_STR + c16 * 8) * 2,
             K + (kb + row) * DKH + c16 * 8);
    }
#pragma unroll
    for (int l = 0; l < 2; l++) {
        int c = tid + l * 256;
        int row = c >> 3, c16 = c & 7;
        cp16(base + KV_HALFS * 2 + (row * KV_STR + c16 * 8) * 2,
             V + (kb + row) * DKH + c16 * 8);
    }
}

__global__ __launch_bounds__(256)
void attn_kernel()
{
    extern __shared__ __half smh[];
    const unsigned smBase = (unsigned)__cvta_generic_to_shared(smh);

    const int tid  = threadIdx.x;
    const int warp = tid >> 5, lane = tid & 31;
    const int grp  = lane >> 2, qi = lane & 3;
    const int hb   = blockIdx.y;
    const int q0   = blockIdx.x * 256;

    const __half* __restrict__ Q = g_q + (size_t)hb * SEQ * DKH;
    const __half* __restrict__ K = g_k + (size_t)hb * SEQ * DKH;
    const __half* __restrict__ V = g_v + (size_t)hb * SEQ * DKH;

    const int row0 = warp * 32;
    const int rowL = tid >> 3, c8 = tid & 7;

    // ---- stage Q into (aliased) smem, ldmatrix to regs, then release smem
#pragma unroll
    for (int l = 0; l < 8; l++) {
        const int r = rowL + l * 32;
        uint4 v = *(const uint4*)&Q[(size_t)(q0 + r) * DKH + c8 * 8];
        *(uint4*)&smh[r * KV_STR + c8 * 8] = v;
    }
    __syncthreads();

    unsigned qf[2][4][4];
    {
        const unsigned qLane = smBase +
            (((row0 + (lane & 7) + ((lane >> 3) & 1) * 8) * KV_STR)
             + (lane >> 4) * 8) * 2;
#pragma unroll
        for (int m = 0; m < 2; m++)
#pragma unroll
            for (int kp = 0; kp < 4; kp++)
                ldsm_x4(qf[m][kp], qLane + m * 16 * (KV_STR * 2) + kp * 32);
    }
    __syncthreads();

    const unsigned kOff = (((lane & 7) * KV_STR) + (lane >> 3) * 8) * 2;
    const unsigned vOff = KV_HALFS * 2 +
        (((lane >> 3) * 8 + (lane & 7)) * KV_STR) * 2;

    float o[2][8][4];
    float rs[2][2];
#pragma unroll
    for (int m = 0; m < 2; m++) {
        rs[m][0] = 0.f; rs[m][1] = 0.f;
#pragma unroll
        for (int ni = 0; ni < 8; ni++)
#pragma unroll
            for (int r = 0; r < 4; r++) o[m][ni][r] = 0.f;
    }

    attn_stage(K, V, smBase, 0, 0, tid);  cp_commit();
    attn_stage(K, V, smBase, 1, 64, tid); cp_commit();
    cp_wait<1>();
    __syncthreads();

    for (int it = 0; it < 32; it++) {
        const int buf = it % 3;
        if (it < 30)
            attn_stage(K, V, smBase, (it + 2) % 3, (size_t)(it + 2) * 64, tid);
        cp_commit();

        const unsigned sB = smBase + (unsigned)buf * (AT_STAGE * 2);

        float s[2][8][4];
#pragma unroll
        for (int m = 0; m < 2; m++)
#pragma unroll
            for (int ni = 0; ni < 8; ni++)
#pragma unroll
                for (int r = 0; r < 4; r++) s[m][ni][r] = 0.f;

#pragma unroll
        for (int kq = 0; kq < 2; kq++) {
#pragma unroll
            for (int ni = 0; ni < 8; ni++) {
                unsigned kf[4];
                ldsm_x4(kf, sB + kOff + (ni * 8 * KV_STR) * 2 + kq * 64);
#pragma unroll
                for (int m = 0; m < 2; m++) {
                    mma_f16(s[m][ni], qf[m][2 * kq],     kf[0], kf[1]);
                    mma_f16(s[m][ni], qf[m][2 * kq + 1], kf[2], kf[3]);
                }
            }
        }

        unsigned ps[2][4][4];
#pragma unroll
        for (int m = 0; m < 2; m++)
#pragma unroll
            for (int tp = 0; tp < 4; tp++) {
                const float* sa = s[m][2 * tp];
                const float* sb = s[m][2 * tp + 1];
                float e0 = __expf(sa[0]), e1 = __expf(sa[1]);
                float e2 = __expf(sa[2]), e3 = __expf(sa[3]);
                float f0 = __expf(sb[0]), f1 = __expf(sb[1]);
                float f2 = __expf(sb[2]), f3 = __expf(sb[3]);
                rs[m][0] += (e0 + e1) + (f0 + f1);
                rs[m][1] += (e2 + e3) + (f2 + f3);
                ps[m][tp][0] = pack_h2(e0, e1);
                ps[m][tp][1] = pack_h2(e2, e3);
                ps[m][tp][2] = pack_h2(f0, f1);
                ps[m][tp][3] = pack_h2(f2, f3);
            }

#pragma unroll
        for (int tq = 0; tq < 2; tq++) {
#pragma unroll
            for (int ni = 0; ni < 8; ni++) {
                unsigned vf[4];
                ldsm_x4t(vf, sB + vOff + (tq * 32 * KV_STR) * 2 + ni * 16);
#pragma unroll
                for (int m = 0; m < 2; m++) {
                    mma_f16(o[m][ni], ps[m][2 * tq],     vf[0], vf[1]);
                    mma_f16(o[m][ni], ps[m][2 * tq + 1], vf[2], vf[3]);
                }
            }
        }

        cp_wait<1>();
        __syncthreads();
    }

#pragma unroll
    for (int m = 0; m < 2; m++)
#pragma unroll
        for (int j = 0; j < 2; j++) {
            float r = rs[m][j];
            r += __shfl_xor_sync(0xffffffffu, r, 1);
            r += __shfl_xor_sync(0xffffffffu, r, 2);
            rs[m][j] = 1.f / r;
        }

    const int h = hb >> 1, b = hb & 1;
#pragma unroll
    for (int m = 0; m < 2; m++) {
        const int sr0 = q0 + row0 + m * 16 + grp;
#pragma unroll
        for (int ni = 0; ni < 8; ni++) {
            const int col = h * DKH + ni * 8 + qi * 2;
            *(unsigned*)&g_ctx[((size_t)(b * SEQ + sr0)) * DM + col] =
                pack_h2(o[m][ni][0] * rs[m][0], o[m][ni][1] * rs[m][0]);
            *(unsigned*)&g_ctx[((size_t)(b * SEQ + sr0 + 8)) * DM + col] =
                pack_h2(o[m][ni][2] * rs[m][1], o[m][ni][3] * rs[m][1]);
        }
    }
}

// ---------------------------------------------------------------------------
extern "C" void kernel_launch(void* const* d_in, const int* in_sizes, int n_in,
                              void* d_out, int out_size)
{
    (void)in_sizes; (void)n_in; (void)out_size;
    const float* query = (const float*)d_in[0];
    const float* key   = (const float*)d_in[1];
    const float* value = (const float*)d_in[2];
    const float* Wq    = (const float*)d_in[3];
    const float* bq    = (const float*)d_in[4];
    const float* Wo    = (const float*)d_in[5];
    const float* bo    = (const float*)d_in[6];
    float* out = (float*)d_out;

    cudaFuncSetAttribute(gemm_kernel<0>,
                         cudaFuncAttributeMaxDynamicSharedMemorySize, GEMM_SMEM);
    cudaFuncSetAttribute(gemm_kernel<1>,
                         cudaFuncAttributeMaxDynamicSharedMemorySize, GEMM_SMEM);
    cudaFuncSetAttribute(attn_kernel,
                         cudaFuncAttributeMaxDynamicSharedMemorySize,
                         ATT_SMEM_BYTES);

    dim3 blk(256);
    cvt_kernel<<<dim3(1024, 1, 5), blk>>>(query, key, value, Wq, Wo);
    gemm_kernel<0><<<dim3(DM / 128, MROWS / 128, 3), blk, GEMM_SMEM>>>(bq, nullptr);
    attn_kernel<<<dim3(SEQ / 256, HEADS * BATCH), blk, ATT_SMEM_BYTES>>>();
    gemm_kernel<1><<<dim3(DM / 128, MROWS / 128, 1), blk, GEMM_SMEM>>>(bo, out);
}

// round 14
// speedup vs baseline: 1.1223x; 1.0825x over previous
#include <cuda_runtime.h>
#include <cuda_fp16.h>
#include <math.h>
#include <stdint.h>

#define DM     1024
#define HEADS  16
#define DKH    64
#define BATCH  2
#define SEQ    2048
#define MROWS  (BATCH*SEQ)   // 4096

// Scratch (device globals; allocation-free per harness rules)
__device__ __half g_q[HEADS*BATCH*SEQ*DKH];    // head-layout projections
__device__ __half g_k[HEADS*BATCH*SEQ*DKH];
__device__ __half g_v[HEADS*BATCH*SEQ*DKH];
__device__ __half g_ctx[(size_t)MROWS*DM];     // attention output (concat)
__device__ __half g_xq[(size_t)MROWS*DM];      // fp16 copies of inputs
__device__ __half g_xk[(size_t)MROWS*DM];
__device__ __half g_xv[(size_t)MROWS*DM];
__device__ __half g_wq[(size_t)DM*DM];         // fp16 weights
__device__ __half g_wo[(size_t)DM*DM];

// ---- helpers --------------------------------------------------------------
__device__ __forceinline__ unsigned pack_h2(float a, float b) {
    __half2 h = __floats2half2_rn(a, b);
    return *reinterpret_cast<unsigned*>(&h);
}
__device__ __forceinline__ uint2 cvt_f4h(float4 v) {
    uint2 r; r.x = pack_h2(v.x, v.y); r.y = pack_h2(v.z, v.w); return r;
}
__device__ __forceinline__ void mma_f16(float d[4], const unsigned a[4],
                                        unsigned b0, unsigned b1) {
    asm("mma.sync.aligned.m16n8k16.row.col.f32.f16.f16.f32 "
        "{%0,%1,%2,%3}, {%4,%5,%6,%7}, {%8,%9}, {%0,%1,%2,%3};"
        : "+f"(d[0]), "+f"(d[1]), "+f"(d[2]), "+f"(d[3])
        : "r"(a[0]), "r"(a[1]), "r"(a[2]), "r"(a[3]), "r"(b0), "r"(b1));
}
__device__ __forceinline__ void ldsm_x4(unsigned r[4], unsigned saddr) {
    asm volatile("ldmatrix.sync.aligned.m8n8.x4.shared.b16 {%0,%1,%2,%3}, [%4];"
                 : "=r"(r[0]), "=r"(r[1]), "=r"(r[2]), "=r"(r[3])
                 : "r"(saddr));
}
__device__ __forceinline__ void ldsm_x4t(unsigned r[4], unsigned saddr) {
    asm volatile("ldmatrix.sync.aligned.m8n8.x4.trans.shared.b16 {%0,%1,%2,%3}, [%4];"
                 : "=r"(r[0]), "=r"(r[1]), "=r"(r[2]), "=r"(r[3])
                 : "r"(saddr));
}
__device__ __forceinline__ void cp16(unsigned dst, const void* src) {
    asm volatile("cp.async.cg.shared.global [%0], [%1], 16;"
                 :: "r"(dst), "l"(src));
}
__device__ __forceinline__ void cp_commit() {
    asm volatile("cp.async.commit_group;" ::: "memory");
}
template<int N>
__device__ __forceinline__ void cp_wait() {
    asm volatile("cp.async.wait_group %0;" :: "n"(N) : "memory");
}

// ---------------------------------------------------------------------------
// f32 -> f16 conversion: z selects {query,key,value,Wq,Wo}
// ---------------------------------------------------------------------------
__global__ void cvt_kernel(const float* __restrict__ q,
                           const float* __restrict__ k,
                           const float* __restrict__ v,
                           const float* __restrict__ wq,
                           const float* __restrict__ wo)
{
    const int z = blockIdx.z;
    const float* src; __half* dst; int nf4;
    if      (z == 0) { src = q;  dst = g_xq; nf4 = MROWS * DM / 4; }
    else if (z == 1) { src = k;  dst = g_xk; nf4 = MROWS * DM / 4; }
    else if (z == 2) { src = v;  dst = g_xv; nf4 = MROWS * DM / 4; }
    else if (z == 3) { src = wq; dst = g_wq; nf4 = DM * DM / 4; }
    else             { src = wo; dst = g_wo; nf4 = DM * DM / 4; }
    for (int i = blockIdx.x * blockDim.x + threadIdx.x; i < nf4;
         i += gridDim.x * blockDim.x) {
        float4 v4 = ((const float4*)src)[i];
        ((uint2*)dst)[i] = cvt_f4h(v4);
    }
}

// ---------------------------------------------------------------------------
// fp16 GEMM, 5-stage cp.async ring, prefetch distance 3, wait_group<1>,
// __syncthreads only every SECOND iteration (warps free-run 2 stages and
// dephase, overlapping LDSM crossbar bursts with tensor bursts).
// CTA 128x128, 8 warps (2m x 4n), warp tile 64x32, k-stage 32.
// MODE 0: A = g_x{q,k,v} (z), B = g_wq; -> head layout (__half);
//         q (z==0) output scaled by log2(e)/sqrt(SEQ) (for exp2f in attn).
// MODE 1: A = g_ctx, B = g_wo; -> f32 out + bias.
// ---------------------------------------------------------------------------
#define GA_STR 40
#define GB_STR 136
#define GA_HALFS (128 * GA_STR)            // 5120
#define GB_HALFS (32 * GB_STR)             // 4352
#define G_STAGE  (GA_HALFS + GB_HALFS)     // 9472 halfs
#define GEMM_SMEM (5 * G_STAGE * 2)        // 94720 bytes

__device__ __forceinline__ void gemm_stage(const __half* __restrict__ A,
                                           const __half* __restrict__ W,
                                           unsigned smBase, int buf, int kt,
                                           int tid)
{
    const unsigned aB = smBase + (unsigned)buf * (G_STAGE * 2);
    const unsigned bB = aB + GA_HALFS * 2;
#pragma unroll
    for (int l = 0; l < 2; l++) {          // A: 128 rows x 32 halfs = 512 chunks
        int c = tid + l * 256;
        int row = c >> 2, c16 = c & 3;
        cp16(aB + (row * GA_STR + c16 * 8) * 2,
             A + (size_t)row * DM + kt + c16 * 8);
    }
#pragma unroll
    for (int l = 0; l < 2; l++) {          // B: 32 rows x 128 halfs = 512 chunks
        int c = tid + l * 256;
        int row = c >> 4, c16 = c & 15;
        cp16(bB + (row * GB_STR + c16 * 8) * 2,
             W + (size_t)(kt + row) * DM + c16 * 8);
    }
}

template<int MODE>
__global__ __launch_bounds__(256, 2)
void gemm_kernel(const float* __restrict__ bias, float* __restrict__ Cout)
{
    extern __shared__ __half smh[];
    const unsigned smBase = (unsigned)__cvta_generic_to_shared(smh);

    const int tid  = threadIdx.x;
    const int warp = tid >> 5, lane = tid & 31;
    const int wm = warp >> 2, wn = warp & 3;
    const int grp = lane >> 2, qi = lane & 3;

    const int z = (MODE == 0) ? blockIdx.z : 0;
    const int gm0 = blockIdx.y * 128;
    const int gn0 = blockIdx.x * 128;

    const __half* __restrict__ A =
        ((MODE == 1) ? g_ctx : (z == 0 ? g_xq : (z == 1 ? g_xk : g_xv)))
        + (size_t)gm0 * DM;
    const __half* __restrict__ W =
        ((MODE == 0) ? g_wq : g_wo) + gn0;

    // ldmatrix lane bases (byte offsets within a stage)
    const unsigned aOff =
        (((wm * 64 + (lane & 7) + ((lane >> 3) & 1) * 8) * GA_STR)
         + (lane >> 4) * 8) * 2;
    const unsigned bOff = GA_HALFS * 2 +
        ((((lane >> 3) * 8 + (lane & 7)) * GB_STR) + wn * 32) * 2;

    float d[4][4][4];
#pragma unroll
    for (int mi = 0; mi < 4; mi++)
#pragma unroll
        for (int ni = 0; ni < 4; ni++)
#pragma unroll
            for (int r = 0; r < 4; r++) d[mi][ni][r] = 0.f;

    // prologue: stages 0, 1, 2 (prefetch distance 3)
    gemm_stage(A, W, smBase, 0, 0,  tid); cp_commit();
    gemm_stage(A, W, smBase, 1, 32, tid); cp_commit();
    gemm_stage(A, W, smBase, 2, 64, tid); cp_commit();
    cp_wait<1>();          // stages 0,1 confirmed
    __syncthreads();

    for (int it = 0; it < 32; it++) {
        const int buf = it % 5;
        if (it < 29)
            gemm_stage(A, W, smBase, (it + 3) % 5, (it + 3) * 32, tid);
        cp_commit();       // commit every iter (uniform group counting)

        const unsigned sB = smBase + (unsigned)buf * (G_STAGE * 2);
        unsigned bf[4][4];
#pragma unroll
        for (int ni = 0; ni < 4; ni++)
            ldsm_x4t(bf[ni], sB + bOff + ni * 16);
#pragma unroll
        for (int kp = 0; kp < 2; kp++) {
            unsigned af[4][4];
#pragma unroll
            for (int mi = 0; mi < 4; mi++)
                ldsm_x4(af[mi], sB + aOff + mi * 16 * (GA_STR * 2) + kp * 32);
#pragma unroll
            for (int mi = 0; mi < 4; mi++)
#pragma unroll
                for (int ni = 0; ni < 4; ni++)
                    mma_f16(d[mi][ni], af[mi], bf[ni][kp * 2], bf[ni][kp * 2 + 1]);
        }

        cp_wait<1>();
        if (it & 1) __syncthreads();   // bar every 2 iters (safety: see proof)
    }

    // ---- epilogue
    // q output carries log2(e)/sqrt(SEQ) so attention can use exp2f.
    const float qsc = (MODE == 0 && z == 0)
                      ? 1.4426950408889634f * rsqrtf((float)SEQ) : 1.0f;
#pragma unroll
    for (int ni = 0; ni < 4; ni++) {
        const int gcol = gn0 + wn * 32 + ni * 8 + qi * 2;
        const float b0 = bias[gcol], b1 = bias[gcol + 1];
#pragma unroll
        for (int mi = 0; mi < 4; mi++) {
            const int gr = gm0 + wm * 64 + mi * 16 + grp;
#pragma unroll
            for (int hh = 0; hh < 2; hh++) {
                const int gm = gr + hh * 8;
                float v0 = d[mi][ni][hh * 2 + 0] + b0;
                float v1 = d[mi][ni][hh * 2 + 1] + b1;
                if (MODE == 0) {
                    v0 *= qsc; v1 *= qsc;
                    __half* out = (z == 0) ? g_q : (z == 1) ? g_k : g_v;
                    const int h = gcol >> 6, dd = gcol & 63;
                    const int b = gm >> 11, s = gm & (SEQ - 1);
                    *(unsigned*)&out[(((size_t)h * BATCH + b) * SEQ + s) * DKH + dd]
                        = pack_h2(v0, v1);
                } else {
                    *(float2*)&Cout[(size_t)gm * DM + gcol] = make_float2(v0, v1);
                }
            }
        }
    }
}

// ---------------------------------------------------------------------------
// fp16 flash attention per (h,b): BQ=256, 8 warps x 32 q-rows; Q in regs.
// K/V: 5-stage cp.async ring, distance 3, wait<1>, bar every 2 iters.
// Scores come pre-scaled by log2(e)/sqrt(SEQ) -> exp2f (pure MUFU.EX2).
// ---------------------------------------------------------------------------
#define KV_STR 72
#define KV_HALFS (64 * KV_STR)              // 4608 halfs (one K or V tile)
#define AT_STAGE (2 * KV_HALFS)             // 9216 halfs per stage
#define ATT_SMEM_BYTES (5 * AT_STAGE * 2)   // 92160 bytes

__device__ __forceinline__ void attn_stage(const __half* __restrict__ K,
                                           const __half* __restrict__ V,
                                           unsigned smBase, int buf,
                                           size_t kb, int tid)
{
    const unsigned base = smBase + (unsigned)buf * (AT_STAGE * 2);
#pragma unroll
    for (int l = 0; l < 2; l++) {
        int c = tid + l * 256;
        int row = c >> 3, c16 = c & 7;
        cp16(base + (row * KV_STR + c16 * 8) * 2,
             K + (kb + row) * DKH + c16 * 8);
    }
#pragma unroll
    for (int l = 0; l < 2; l++) {
        int c = tid + l * 256;
        int row = c >> 3, c16 = c & 7;
        cp16(base + KV_HALFS * 2 + (row * KV_STR + c16 * 8) * 2,
             V + (kb + row) * DKH + c16 * 8);
    }
}

__global__ __launch_bounds__(256)
void attn_kernel()
{
    extern __shared__ __half smh[];
    const unsigned smBase = (unsigned)__cvta_generic_to_shared(smh);

    const int tid  = threadIdx.x;
    const int warp = tid >> 5, lane = tid & 31;
    const int grp  = lane >> 2, qi = lane & 3;
    const int hb   = blockIdx.y;
    const int q0   = blockIdx.x * 256;

    const __half* __restrict__ Q = g_q + (size_t)hb * SEQ * DKH;
    const __half* __restrict__ K = g_k + (size_t)hb * SEQ * DKH;
    const __half* __restrict__ V = g_v + (size_t)hb * SEQ * DKH;

    const int row0 = warp * 32;
    const int rowL = tid >> 3, c8 = tid & 7;

    // ---- stage Q into (aliased) smem, ldmatrix to regs, then release smem
#pragma unroll
    for (int l = 0; l < 8; l++) {
        const int r = rowL + l * 32;
        uint4 v = *(const uint4*)&Q[(size_t)(q0 + r) * DKH + c8 * 8];
        *(uint4*)&smh[r * KV_STR + c8 * 8] = v;
    }
    __syncthreads();

    unsigned qf[2][4][4];
    {
        const unsigned qLane = smBase +
            (((row0 + (lane & 7) + ((lane >> 3) & 1) * 8) * KV_STR)
             + (lane >> 4) * 8) * 2;
#pragma unroll
        for (int m = 0; m < 2; m++)
#pragma unroll
            for (int kp = 0; kp < 4; kp++)
                ldsm_x4(qf[m][kp], qLane + m * 16 * (KV_STR * 2) + kp * 32);
    }
    __syncthreads();   // all warps done with Q before cp.async overwrites

    const unsigned kOff = (((lane & 7) * KV_STR) + (lane >> 3) * 8) * 2;
    const unsigned vOff = KV_HALFS * 2 +
        (((lane >> 3) * 8 + (lane & 7)) * KV_STR) * 2;

    float o[2][8][4];
    float rs[2][2];
#pragma unroll
    for (int m = 0; m < 2; m++) {
        rs[m][0] = 0.f; rs[m][1] = 0.f;
#pragma unroll
        for (int ni = 0; ni < 8; ni++)
#pragma unroll
            for (int r = 0; r < 4; r++) o[m][ni][r] = 0.f;
    }

    // prologue: stages 0, 1, 2
    attn_stage(K, V, smBase, 0, 0,   tid); cp_commit();
    attn_stage(K, V, smBase, 1, 64,  tid); cp_commit();
    attn_stage(K, V, smBase, 2, 128, tid); cp_commit();
    cp_wait<1>();
    __syncthreads();

    for (int it = 0; it < 32; it++) {
        const int buf = it % 5;
        if (it < 29)
            attn_stage(K, V, smBase, (it + 3) % 5, (size_t)(it + 3) * 64, tid);
        cp_commit();

        const unsigned sB = smBase + (unsigned)buf * (AT_STAGE * 2);

        // ---- S = Q @ K^T (pre-scaled by log2e/sqrt(SEQ))
        float s[2][8][4];
#pragma unroll
        for (int m = 0; m < 2; m++)
#pragma unroll
            for (int ni = 0; ni < 8; ni++)
#pragma unroll
                for (int r = 0; r < 4; r++) s[m][ni][r] = 0.f;

#pragma unroll
        for (int kq = 0; kq < 2; kq++) {
#pragma unroll
            for (int ni = 0; ni < 8; ni++) {
                unsigned kf[4];
                ldsm_x4(kf, sB + kOff + (ni * 8 * KV_STR) * 2 + kq * 64);
#pragma unroll
                for (int m = 0; m < 2; m++) {
                    mma_f16(s[m][ni], qf[m][2 * kq],     kf[0], kf[1]);
                    mma_f16(s[m][ni], qf[m][2 * kq + 1], kf[2], kf[3]);
                }
            }
        }

        // ---- P = exp2(S): lane-local half2 packs are the PV A-frags
        unsigned ps[2][4][4];
#pragma unroll
        for (int m = 0; m < 2; m++)
#pragma unroll
            for (int tp = 0; tp < 4; tp++) {
                const float* sa = s[m][2 * tp];
                const float* sb = s[m][2 * tp + 1];
                float e0 = exp2f(sa[0]), e1 = exp2f(sa[1]);
                float e2 = exp2f(sa[2]), e3 = exp2f(sa[3]);
                float f0 = exp2f(sb[0]), f1 = exp2f(sb[1]);
                float f2 = exp2f(sb[2]), f3 = exp2f(sb[3]);
                rs[m][0] += (e0 + e1) + (f0 + f1);
                rs[m][1] += (e2 + e3) + (f2 + f3);
                ps[m][tp][0] = pack_h2(e0, e1);
                ps[m][tp][1] = pack_h2(e2, e3);
                ps[m][tp][2] = pack_h2(f0, f1);
                ps[m][tp][3] = pack_h2(f2, f3);
            }

        // ---- O += P @ V
#pragma unroll
        for (int tq = 0; tq < 2; tq++) {
#pragma unroll
            for (int ni = 0; ni < 8; ni++) {
                unsigned vf[4];
                ldsm_x4t(vf, sB + vOff + (tq * 32 * KV_STR) * 2 + ni * 16);
#pragma unroll
                for (int m = 0; m < 2; m++) {
                    mma_f16(o[m][ni], ps[m][2 * tq],     vf[0], vf[1]);
                    mma_f16(o[m][ni], ps[m][2 * tq + 1], vf[2], vf[3]);
                }
            }
        }

        cp_wait<1>();
        if (it & 1) __syncthreads();
    }

    // rowsum reduce over the 4 qi lanes
#pragma unroll
    for (int m = 0; m < 2; m++)
#pragma unroll
        for (int j = 0; j < 2; j++) {
            float r = rs[m][j];
            r += __shfl_xor_sync(0xffffffffu, r, 1);
            r += __shfl_xor_sync(0xffffffffu, r, 2);
            rs[m][j] = 1.f / r;
        }

    // write O (fp16) to concat layout g_ctx[(b*S+s)*1024 + h*64 + dv]
    const int h = hb >> 1, b = hb & 1;
#pragma unroll
    for (int m = 0; m < 2; m++) {
        const int sr0 = q0 + row0 + m * 16 + grp;
#pragma unroll
        for (int ni = 0; ni < 8; ni++) {
            const int col = h * DKH + ni * 8 + qi * 2;
            *(unsigned*)&g_ctx[((size_t)(b * SEQ + sr0)) * DM + col] =
                pack_h2(o[m][ni][0] * rs[m][0], o[m][ni][1] * rs[m][0]);
            *(unsigned*)&g_ctx[((size_t)(b * SEQ + sr0 + 8)) * DM + col] =
                pack_h2(o[m][ni][2] * rs[m][1], o[m][ni][3] * rs[m][1]);
        }
    }
}

// ---------------------------------------------------------------------------
extern "C" void kernel_launch(void* const* d_in, const int* in_sizes, int n_in,
                              void* d_out, int out_size)
{
    (void)in_sizes; (void)n_in; (void)out_size;
    const float* query = (const float*)d_in[0];
    const float* key   = (const float*)d_in[1];
    const float* value = (const float*)d_in[2];
    const float* Wq    = (const float*)d_in[3];
    const float* bq    = (const float*)d_in[4];
    const float* Wo    = (const float*)d_in[5];
    const float* bo    = (const float*)d_in[6];
    float* out = (float*)d_out;

    cudaFuncSetAttribute(gemm_kernel<0>,
                         cudaFuncAttributeMaxDynamicSharedMemorySize, GEMM_SMEM);
    cudaFuncSetAttribute(gemm_kernel<1>,
                         cudaFuncAttributeMaxDynamicSharedMemorySize, GEMM_SMEM);
    cudaFuncSetAttribute(attn_kernel,
                         cudaFuncAttributeMaxDynamicSharedMemorySize,
                         ATT_SMEM_BYTES);

    dim3 blk(256);
    cvt_kernel<<<dim3(1024, 1, 5), blk>>>(query, key, value, Wq, Wo);
    gemm_kernel<0><<<dim3(DM / 128, MROWS / 128, 3), blk, GEMM_SMEM>>>(bq, nullptr);
    attn_kernel<<<dim3(SEQ / 256, HEADS * BATCH), blk, ATT_SMEM_BYTES>>>();
    gemm_kernel<1><<<dim3(DM / 128, MROWS / 128, 1), blk, GEMM_SMEM>>>(bo, out);
}

// round 15
// speedup vs baseline: 1.1508x; 1.0254x over previous
#include <cuda_runtime.h>
#include <cuda_fp16.h>
#include <math.h>
#include <stdint.h>

#define DM     1024
#define HEADS  16
#define DKH    64
#define BATCH  2
#define SEQ    2048
#define MROWS  (BATCH*SEQ)   // 4096

// Scratch (device globals; allocation-free per harness rules)
__device__ __half g_q[HEADS*BATCH*SEQ*DKH];    // head-layout projections
__device__ __half g_k[HEADS*BATCH*SEQ*DKH];
__device__ __half g_v[HEADS*BATCH*SEQ*DKH];
__device__ __half g_ctx[(size_t)MROWS*DM];     // attention output (concat)
__device__ __half g_xq[(size_t)MROWS*DM];      // fp16 copies of inputs
__device__ __half g_xk[(size_t)MROWS*DM];
__device__ __half g_xv[(size_t)MROWS*DM];
__device__ __half g_wq[(size_t)DM*DM];         // fp16 weights
__device__ __half g_wo[(size_t)DM*DM];

// ---- helpers --------------------------------------------------------------
__device__ __forceinline__ unsigned pack_h2(float a, float b) {
    __half2 h = __floats2half2_rn(a, b);
    return *reinterpret_cast<unsigned*>(&h);
}
__device__ __forceinline__ uint2 cvt_f4h(float4 v) {
    uint2 r; r.x = pack_h2(v.x, v.y); r.y = pack_h2(v.z, v.w); return r;
}
__device__ __forceinline__ void mma_f16(float d[4], const unsigned a[4],
                                        unsigned b0, unsigned b1) {
    asm("mma.sync.aligned.m16n8k16.row.col.f32.f16.f16.f32 "
        "{%0,%1,%2,%3}, {%4,%5,%6,%7}, {%8,%9}, {%0,%1,%2,%3};"
        : "+f"(d[0]), "+f"(d[1]), "+f"(d[2]), "+f"(d[3])
        : "r"(a[0]), "r"(a[1]), "r"(a[2]), "r"(a[3]), "r"(b0), "r"(b1));
}
__device__ __forceinline__ void ldsm_x4(unsigned r[4], unsigned saddr) {
    asm volatile("ldmatrix.sync.aligned.m8n8.x4.shared.b16 {%0,%1,%2,%3}, [%4];"
                 : "=r"(r[0]), "=r"(r[1]), "=r"(r[2]), "=r"(r[3])
                 : "r"(saddr));
}
__device__ __forceinline__ void ldsm_x4t(unsigned r[4], unsigned saddr) {
    asm volatile("ldmatrix.sync.aligned.m8n8.x4.trans.shared.b16 {%0,%1,%2,%3}, [%4];"
                 : "=r"(r[0]), "=r"(r[1]), "=r"(r[2]), "=r"(r[3])
                 : "r"(saddr));
}
__device__ __forceinline__ void cp16(unsigned dst, const void* src) {
    asm volatile("cp.async.cg.shared.global [%0], [%1], 16;"
                 :: "r"(dst), "l"(src));
}
__device__ __forceinline__ void cp_commit() {
    asm volatile("cp.async.commit_group;" ::: "memory");
}
template<int N>
__device__ __forceinline__ void cp_wait() {
    asm volatile("cp.async.wait_group %0;" :: "n"(N) : "memory");
}

// ---------------------------------------------------------------------------
// f32 -> f16 conversion: z selects {query,key,value,Wq,Wo}
// ---------------------------------------------------------------------------
__global__ void cvt_kernel(const float* __restrict__ q,
                           const float* __restrict__ k,
                           const float* __restrict__ v,
                           const float* __restrict__ wq,
                           const float* __restrict__ wo)
{
    const int z = blockIdx.z;
    const float* src; __half* dst; int nf4;
    if      (z == 0) { src = q;  dst = g_xq; nf4 = MROWS * DM / 4; }
    else if (z == 1) { src = k;  dst = g_xk; nf4 = MROWS * DM / 4; }
    else if (z == 2) { src = v;  dst = g_xv; nf4 = MROWS * DM / 4; }
    else if (z == 3) { src = wq; dst = g_wq; nf4 = DM * DM / 4; }
    else             { src = wo; dst = g_wo; nf4 = DM * DM / 4; }
    for (int i = blockIdx.x * blockDim.x + threadIdx.x; i < nf4;
         i += gridDim.x * blockDim.x) {
        float4 v4 = ((const float4*)src)[i];
        ((uint2*)dst)[i] = cvt_f4h(v4);
    }
}

// ---------------------------------------------------------------------------
// q/k/v projection GEMM: CTA 128x256, warp tile 64x64 (2m x 4n warps).
// Crossbar bytes/MAC = 0.086 (was 0.125) -> tensor ceiling ~74%.
// 5-stage cp.async ring, distance 3, wait<1>, bar every 2 iters. 1 CTA/SM.
// A smem [128][40] halfs, B smem [32][264] halfs (stride 264: x4t banks 4r,
// conflict-free). q (z==0) output scaled by log2(e)/sqrt(SEQ).
// ---------------------------------------------------------------------------
#define QA_STR 40
#define QB_STR 264
#define QA_HALFS (128 * QA_STR)            // 5120
#define QB_HALFS (32 * QB_STR)             // 8448
#define Q_STAGE  (QA_HALFS + QB_HALFS)     // 13568 halfs
#define QKV_SMEM (5 * Q_STAGE * 2)         // 135680 bytes

__device__ __forceinline__ void qkv_stage(const __half* __restrict__ A,
                                          const __half* __restrict__ W,
                                          unsigned smBase, int buf, int kt,
                                          int tid)
{
    const unsigned aB = smBase + (unsigned)buf * (Q_STAGE * 2);
    const unsigned bB = aB + QA_HALFS * 2;
#pragma unroll
    for (int l = 0; l < 2; l++) {          // A: 128 rows x 32 halfs = 512 chunks
        int c = tid + l * 256;
        int row = c >> 2, c16 = c & 3;
        cp16(aB + (row * QA_STR + c16 * 8) * 2,
             A + (size_t)row * DM + kt + c16 * 8);
    }
#pragma unroll
    for (int l = 0; l < 4; l++) {          // B: 32 rows x 256 halfs = 1024 chunks
        int c = tid + l * 256;
        int row = c >> 5, c16 = c & 31;
        cp16(bB + (row * QB_STR + c16 * 8) * 2,
             W + (size_t)(kt + row) * DM + c16 * 8);
    }
}

__global__ __launch_bounds__(256, 1)
void gemm_qkv(const float* __restrict__ bias)
{
    extern __shared__ __half smh[];
    const unsigned smBase = (unsigned)__cvta_generic_to_shared(smh);

    const int tid  = threadIdx.x;
    const int warp = tid >> 5, lane = tid & 31;
    const int wm = warp >> 2, wn = warp & 3;
    const int grp = lane >> 2, qi = lane & 3;

    const int z = blockIdx.z;
    const int gm0 = blockIdx.y * 128;
    const int gn0 = blockIdx.x * 256;

    const __half* __restrict__ A =
        (z == 0 ? g_xq : (z == 1 ? g_xk : g_xv)) + (size_t)gm0 * DM;
    const __half* __restrict__ W = g_wq + gn0;

    const unsigned aOff =
        (((wm * 64 + (lane & 7) + ((lane >> 3) & 1) * 8) * QA_STR)
         + (lane >> 4) * 8) * 2;
    const unsigned bOff = QA_HALFS * 2 +
        ((((lane >> 3) * 8 + (lane & 7)) * QB_STR) + wn * 64) * 2;

    float d[4][8][4];
#pragma unroll
    for (int mi = 0; mi < 4; mi++)
#pragma unroll
        for (int ni = 0; ni < 8; ni++)
#pragma unroll
            for (int r = 0; r < 4; r++) d[mi][ni][r] = 0.f;

    // prologue: stages 0, 1, 2
    qkv_stage(A, W, smBase, 0, 0,  tid); cp_commit();
    qkv_stage(A, W, smBase, 1, 32, tid); cp_commit();
    qkv_stage(A, W, smBase, 2, 64, tid); cp_commit();
    cp_wait<1>();
    __syncthreads();

    for (int it = 0; it < 32; it++) {
        const int buf = it % 5;
        if (it < 29)
            qkv_stage(A, W, smBase, (it + 3) % 5, (it + 3) * 32, tid);
        cp_commit();

        const unsigned sB = smBase + (unsigned)buf * (Q_STAGE * 2);
        unsigned bf[8][4];
#pragma unroll
        for (int ni = 0; ni < 8; ni++)
            ldsm_x4t(bf[ni], sB + bOff + ni * 16);
#pragma unroll
        for (int kp = 0; kp < 2; kp++) {
            unsigned af[4][4];
#pragma unroll
            for (int mi = 0; mi < 4; mi++)
                ldsm_x4(af[mi], sB + aOff + mi * 16 * (QA_STR * 2) + kp * 32);
#pragma unroll
            for (int mi = 0; mi < 4; mi++)
#pragma unroll
                for (int ni = 0; ni < 8; ni++)
                    mma_f16(d[mi][ni], af[mi], bf[ni][kp * 2], bf[ni][kp * 2 + 1]);
        }

        cp_wait<1>();
        if (it & 1) __syncthreads();
    }

    // ---- epilogue: scatter to head layout (__half); q carries log2e/sqrt(S)
    const float qsc = (z == 0) ? 1.4426950408889634f * rsqrtf((float)SEQ) : 1.0f;
    __half* out = (z == 0) ? g_q : (z == 1) ? g_k : g_v;
#pragma unroll
    for (int ni = 0; ni < 8; ni++) {
        const int gcol = gn0 + wn * 64 + ni * 8 + qi * 2;
        const float b0 = bias[gcol], b1 = bias[gcol + 1];
        const int h = gcol >> 6, dd = gcol & 63;
#pragma unroll
        for (int mi = 0; mi < 4; mi++) {
            const int gr = gm0 + wm * 64 + mi * 16 + grp;
#pragma unroll
            for (int hh = 0; hh < 2; hh++) {
                const int gm = gr + hh * 8;
                const float v0 = (d[mi][ni][hh * 2 + 0] + b0) * qsc;
                const float v1 = (d[mi][ni][hh * 2 + 1] + b1) * qsc;
                const int b = gm >> 11, s = gm & (SEQ - 1);
                *(unsigned*)&out[(((size_t)h * BATCH + b) * SEQ + s) * DKH + dd]
                    = pack_h2(v0, v1);
            }
        }
    }
}

// ---------------------------------------------------------------------------
// Output projection GEMM (R14-proven): CTA 128x128, 5-stage ring, bar/2.
// ---------------------------------------------------------------------------
#define GA_STR 40
#define GB_STR 136
#define GA_HALFS (128 * GA_STR)            // 5120
#define GB_HALFS (32 * GB_STR)             // 4352
#define G_STAGE  (GA_HALFS + GB_HALFS)     // 9472 halfs
#define GEMM_SMEM (5 * G_STAGE * 2)        // 94720 bytes

__device__ __forceinline__ void gemm_stage(const __half* __restrict__ A,
                                           const __half* __restrict__ W,
                                           unsigned smBase, int buf, int kt,
                                           int tid)
{
    const unsigned aB = smBase + (unsigned)buf * (G_STAGE * 2);
    const unsigned bB = aB + GA_HALFS * 2;
#pragma unroll
    for (int l = 0; l < 2; l++) {
        int c = tid + l * 256;
        int row = c >> 2, c16 = c & 3;
        cp16(aB + (row * GA_STR + c16 * 8) * 2,
             A + (size_t)row * DM + kt + c16 * 8);
    }
#pragma unroll
    for (int l = 0; l < 2; l++) {
        int c = tid + l * 256;
        int row = c >> 4, c16 = c & 15;
        cp16(bB + (row * GB_STR + c16 * 8) * 2,
             W + (size_t)(kt + row) * DM + c16 * 8);
    }
}

__global__ __launch_bounds__(256, 2)
void gemm_out(const float* __restrict__ bias, float* __restrict__ Cout)
{
    extern __shared__ __half smh[];
    const unsigned smBase = (unsigned)__cvta_generic_to_shared(smh);

    const int tid  = threadIdx.x;
    const int warp = tid >> 5, lane = tid & 31;
    const int wm = warp >> 2, wn = warp & 3;
    const int grp = lane >> 2, qi = lane & 3;

    const int gm0 = blockIdx.y * 128;
    const int gn0 = blockIdx.x * 128;

    const __half* __restrict__ A = g_ctx + (size_t)gm0 * DM;
    const __half* __restrict__ W = g_wo + gn0;

    const unsigned aOff =
        (((wm * 64 + (lane & 7) + ((lane >> 3) & 1) * 8) * GA_STR)
         + (lane >> 4) * 8) * 2;
    const unsigned bOff = GA_HALFS * 2 +
        ((((lane >> 3) * 8 + (lane & 7)) * GB_STR) + wn * 32) * 2;

    float d[4][4][4];
#pragma unroll
    for (int mi = 0; mi < 4; mi++)
#pragma unroll
        for (int ni = 0; ni < 4; ni++)
#pragma unroll
            for (int r = 0; r < 4; r++) d[mi][ni][r] = 0.f;

    gemm_stage(A, W, smBase, 0, 0,  tid); cp_commit();
    gemm_stage(A, W, smBase, 1, 32, tid); cp_commit();
    gemm_stage(A, W, smBase, 2, 64, tid); cp_commit();
    cp_wait<1>();
    __syncthreads();

    for (int it = 0; it < 32; it++) {
        const int buf = it % 5;
        if (it < 29)
            gemm_stage(A, W, smBase, (it + 3) % 5, (it + 3) * 32, tid);
        cp_commit();

        const unsigned sB = smBase + (unsigned)buf * (G_STAGE * 2);
        unsigned bf[4][4];
#pragma unroll
        for (int ni = 0; ni < 4; ni++)
            ldsm_x4t(bf[ni], sB + bOff + ni * 16);
#pragma unroll
        for (int kp = 0; kp < 2; kp++) {
            unsigned af[4][4];
#pragma unroll
            for (int mi = 0; mi < 4; mi++)
                ldsm_x4(af[mi], sB + aOff + mi * 16 * (GA_STR * 2) + kp * 32);
#pragma unroll
            for (int mi = 0; mi < 4; mi++)
#pragma unroll
                for (int ni = 0; ni < 4; ni++)
                    mma_f16(d[mi][ni], af[mi], bf[ni][kp * 2], bf[ni][kp * 2 + 1]);
        }

        cp_wait<1>();
        if (it & 1) __syncthreads();
    }

#pragma unroll
    for (int ni = 0; ni < 4; ni++) {
        const int gcol = gn0 + wn * 32 + ni * 8 + qi * 2;
        const float b0 = bias[gcol], b1 = bias[gcol + 1];
#pragma unroll
        for (int mi = 0; mi < 4; mi++) {
            const int gr = gm0 + wm * 64 + mi * 16 + grp;
#pragma unroll
            for (int hh = 0; hh < 2; hh++) {
                const int gm = gr + hh * 8;
                *(float2*)&Cout[(size_t)gm * DM + gcol] =
                    make_float2(d[mi][ni][hh * 2 + 0] + b0,
                                d[mi][ni][hh * 2 + 1] + b1);
            }
        }
    }
}

// ---------------------------------------------------------------------------
// fp16 flash attention per (h,b) (R14-proven): BQ=256, 8 warps x 32 q-rows;
// Q in regs; K/V 5-stage cp.async ring, bar every 2 iters; exp2f softmax.
// ---------------------------------------------------------------------------
#define KV_STR 72
#define KV_HALFS (64 * KV_STR)              // 4608 halfs (one K or V tile)
#define AT_STAGE (2 * KV_HALFS)             // 9216 halfs per stage
#define ATT_SMEM_BYTES (5 * AT_STAGE * 2)   // 92160 bytes

__device__ __forceinline__ void attn_stage(const __half* __restrict__ K,
                                           const __half* __restrict__ V,
                                           unsigned smBase, int buf,
                                           size_t kb, int tid)
{
    const unsigned base = smBase + (unsigned)buf * (AT_STAGE * 2);
#pragma unroll
    for (int l = 0; l < 2; l++) {
        int c = tid + l * 256;
        int row = c >> 3, c16 = c & 7;
        cp16(base + (row * KV_STR + c16 * 8) * 2,
             K + (kb + row) * DKH + c16 * 8);
    }
#pragma unroll
    for (int l = 0; l < 2; l++) {
        int c = tid + l * 256;
        int row = c >> 3, c16 = c & 7;
        cp16(base + KV_HALFS * 2 + (row * KV_STR + c16 * 8) * 2,
             V + (kb + row) * DKH + c16 * 8);
    }
}

__global__ __launch_bounds__(256)
void attn_kernel()
{
    extern __shared__ __half smh[];
    const unsigned smBase = (unsigned)__cvta_generic_to_shared(smh);

    const int tid  = threadIdx.x;
    const int warp = tid >> 5, lane = tid & 31;
    const int grp  = lane >> 2, qi = lane & 3;
    const int hb   = blockIdx.y;
    const int q0   = blockIdx.x * 256;

    const __half* __restrict__ Q = g_q + (size_t)hb * SEQ * DKH;
    const __half* __restrict__ K = g_k + (size_t)hb * SEQ * DKH;
    const __half* __restrict__ V = g_v + (size_t)hb * SEQ * DKH;

    const int row0 = warp * 32;
    const int rowL = tid >> 3, c8 = tid & 7;

    // ---- stage Q into (aliased) smem, ldmatrix to regs, then release smem
#pragma unroll
    for (int l = 0; l < 8; l++) {
        const int r = rowL + l * 32;
        uint4 v = *(const uint4*)&Q[(size_t)(q0 + r) * DKH + c8 * 8];
        *(uint4*)&smh[r * KV_STR + c8 * 8] = v;
    }
    __syncthreads();

    unsigned qf[2][4][4];
    {
        const unsigned qLane = smBase +
            (((row0 + (lane & 7) + ((lane >> 3) & 1) * 8) * KV_STR)
             + (lane >> 4) * 8) * 2;
#pragma unroll
        for (int m = 0; m < 2; m++)
#pragma unroll
            for (int kp = 0; kp < 4; kp++)
                ldsm_x4(qf[m][kp], qLane + m * 16 * (KV_STR * 2) + kp * 32);
    }
    __syncthreads();

    const unsigned kOff = (((lane & 7) * KV_STR) + (lane >> 3) * 8) * 2;
    const unsigned vOff = KV_HALFS * 2 +
        (((lane >> 3) * 8 + (lane & 7)) * KV_STR) * 2;

    float o[2][8][4];
    float rs[2][2];
#pragma unroll
    for (int m = 0; m < 2; m++) {
        rs[m][0] = 0.f; rs[m][1] = 0.f;
#pragma unroll
        for (int ni = 0; ni < 8; ni++)
#pragma unroll
            for (int r = 0; r < 4; r++) o[m][ni][r] = 0.f;
    }

    attn_stage(K, V, smBase, 0, 0,   tid); cp_commit();
    attn_stage(K, V, smBase, 1, 64,  tid); cp_commit();
    attn_stage(K, V, smBase, 2, 128, tid); cp_commit();
    cp_wait<1>();
    __syncthreads();

    for (int it = 0; it < 32; it++) {
        const int buf = it % 5;
        if (it < 29)
            attn_stage(K, V, smBase, (it + 3) % 5, (size_t)(it + 3) * 64, tid);
        cp_commit();

        const unsigned sB = smBase + (unsigned)buf * (AT_STAGE * 2);

        float s[2][8][4];
#pragma unroll
        for (int m = 0; m < 2; m++)
#pragma unroll
            for (int ni = 0; ni < 8; ni++)
#pragma unroll
                for (int r = 0; r < 4; r++) s[m][ni][r] = 0.f;

#pragma unroll
        for (int kq = 0; kq < 2; kq++) {
#pragma unroll
            for (int ni = 0; ni < 8; ni++) {
                unsigned kf[4];
                ldsm_x4(kf, sB + kOff + (ni * 8 * KV_STR) * 2 + kq * 64);
#pragma unroll
                for (int m = 0; m < 2; m++) {
                    mma_f16(s[m][ni], qf[m][2 * kq],     kf[0], kf[1]);
                    mma_f16(s[m][ni], qf[m][2 * kq + 1], kf[2], kf[3]);
                }
            }
        }

        unsigned ps[2][4][4];
#pragma unroll
        for (int m = 0; m < 2; m++)
#pragma unroll
            for (int tp = 0; tp < 4; tp++) {
                const float* sa = s[m][2 * tp];
                const float* sb = s[m][2 * tp + 1];
                float e0 = exp2f(sa[0]), e1 = exp2f(sa[1]);
                float e2 = exp2f(sa[2]), e3 = exp2f(sa[3]);
                float f0 = exp2f(sb[0]), f1 = exp2f(sb[1]);
                float f2 = exp2f(sb[2]), f3 = exp2f(sb[3]);
                rs[m][0] += (e0 + e1) + (f0 + f1);
                rs[m][1] += (e2 + e3) + (f2 + f3);
                ps[m][tp][0] = pack_h2(e0, e1);
                ps[m][tp][1] = pack_h2(e2, e3);
                ps[m][tp][2] = pack_h2(f0, f1);
                ps[m][tp][3] = pack_h2(f2, f3);
            }

#pragma unroll
        for (int tq = 0; tq < 2; tq++) {
#pragma unroll
            for (int ni = 0; ni < 8; ni++) {
                unsigned vf[4];
                ldsm_x4t(vf, sB + vOff + (tq * 32 * KV_STR) * 2 + ni * 16);
#pragma unroll
                for (int m = 0; m < 2; m++) {
                    mma_f16(o[m][ni], ps[m][2 * tq],     vf[0], vf[1]);
                    mma_f16(o[m][ni], ps[m][2 * tq + 1], vf[2], vf[3]);
                }
            }
        }

        cp_wait<1>();
        if (it & 1) __syncthreads();
    }

#pragma unroll
    for (int m = 0; m < 2; m++)
#pragma unroll
        for (int j = 0; j < 2; j++) {
            float r = rs[m][j];
            r += __shfl_xor_sync(0xffffffffu, r, 1);
            r += __shfl_xor_sync(0xffffffffu, r, 2);
            rs[m][j] = 1.f / r;
        }

    const int h = hb >> 1, b = hb & 1;
#pragma unroll
    for (int m = 0; m < 2; m++) {
        const int sr0 = q0 + row0 + m * 16 + grp;
#pragma unroll
        for (int ni = 0; ni < 8; ni++) {
            const int col = h * DKH + ni * 8 + qi * 2;
            *(unsigned*)&g_ctx[((size_t)(b * SEQ + sr0)) * DM + col] =
                pack_h2(o[m][ni][0] * rs[m][0], o[m][ni][1] * rs[m][0]);
            *(unsigned*)&g_ctx[((size_t)(b * SEQ + sr0 + 8)) * DM + col] =
                pack_h2(o[m][ni][2] * rs[m][1], o[m][ni][3] * rs[m][1]);
        }
    }
}

// ---------------------------------------------------------------------------
extern "C" void kernel_launch(void* const* d_in, const int* in_sizes, int n_in,
                              void* d_out, int out_size)
{
    (void)in_sizes; (void)n_in; (void)out_size;
    const float* query = (const float*)d_in[0];
    const float* key   = (const float*)d_in[1];
    const float* value = (const float*)d_in[2];
    const float* Wq    = (const float*)d_in[3];
    const float* bq    = (const float*)d_in[4];
    const float* Wo    = (const float*)d_in[5];
    const float* bo    = (const float*)d_in[6];
    float* out = (float*)d_out;

    cudaFuncSetAttribute(gemm_qkv,
                         cudaFuncAttributeMaxDynamicSharedMemorySize, QKV_SMEM);
    cudaFuncSetAttribute(gemm_out,
                         cudaFuncAttributeMaxDynamicSharedMemorySize, GEMM_SMEM);
    cudaFuncSetAttribute(attn_kernel,
                         cudaFuncAttributeMaxDynamicSharedMemorySize,
                         ATT_SMEM_BYTES);

    dim3 blk(256);
    cvt_kernel<<<dim3(1024, 1, 5), blk>>>(query, key, value, Wq, Wo);
    gemm_qkv<<<dim3(DM / 256, MROWS / 128, 3), blk, QKV_SMEM>>>(bq);
    attn_kernel<<<dim3(SEQ / 256, HEADS * BATCH), blk, ATT_SMEM_BYTES>>>();
    gemm_out<<<dim3(DM / 128, MROWS / 128), blk, GEMM_SMEM>>>(bo, out);
}

// round 16
// speedup vs baseline: 1.1834x; 1.0283x over previous
#include <cuda_runtime.h>
#include <cuda_fp16.h>
#include <math.h>
#include <stdint.h>

#define DM     1024
#define HEADS  16
#define DKH    64
#define BATCH  2
#define SEQ    2048
#define MROWS  (BATCH*SEQ)   // 4096

// Scratch (device globals; allocation-free per harness rules)
__device__ __half g_q[HEADS*BATCH*SEQ*DKH];    // head-layout projections
__device__ __half g_k[HEADS*BATCH*SEQ*DKH];
__device__ __half g_v[HEADS*BATCH*SEQ*DKH];
__device__ __half g_ctx[(size_t)MROWS*DM];     // attention output (concat)
__device__ __half g_xq[(size_t)MROWS*DM];      // fp16 copies of inputs
__device__ __half g_xk[(size_t)MROWS*DM];
__device__ __half g_xv[(size_t)MROWS*DM];
__device__ __half g_wq[(size_t)DM*DM];         // fp16 weights
__device__ __half g_wo[(size_t)DM*DM];

// ---- helpers --------------------------------------------------------------
__device__ __forceinline__ unsigned pack_h2(float a, float b) {
    __half2 h = __floats2half2_rn(a, b);
    return *reinterpret_cast<unsigned*>(&h);
}
__device__ __forceinline__ uint2 cvt_f4h(float4 v) {
    uint2 r; r.x = pack_h2(v.x, v.y); r.y = pack_h2(v.z, v.w); return r;
}
__device__ __forceinline__ void mma_f16(float d[4], const unsigned a[4],
                                        unsigned b0, unsigned b1) {
    asm("mma.sync.aligned.m16n8k16.row.col.f32.f16.f16.f32 "
        "{%0,%1,%2,%3}, {%4,%5,%6,%7}, {%8,%9}, {%0,%1,%2,%3};"
        : "+f"(d[0]), "+f"(d[1]), "+f"(d[2]), "+f"(d[3])
        : "r"(a[0]), "r"(a[1]), "r"(a[2]), "r"(a[3]), "r"(b0), "r"(b1));
}
__device__ __forceinline__ void ldsm_x4(unsigned r[4], unsigned saddr) {
    asm volatile("ldmatrix.sync.aligned.m8n8.x4.shared.b16 {%0,%1,%2,%3}, [%4];"
                 : "=r"(r[0]), "=r"(r[1]), "=r"(r[2]), "=r"(r[3])
                 : "r"(saddr));
}
__device__ __forceinline__ void ldsm_x4t(unsigned r[4], unsigned saddr) {
    asm volatile("ldmatrix.sync.aligned.m8n8.x4.trans.shared.b16 {%0,%1,%2,%3}, [%4];"
                 : "=r"(r[0]), "=r"(r[1]), "=r"(r[2]), "=r"(r[3])
                 : "r"(saddr));
}
__device__ __forceinline__ void cp16(unsigned dst, const void* src) {
    asm volatile("cp.async.cg.shared.global [%0], [%1], 16;"
                 :: "r"(dst), "l"(src));
}
__device__ __forceinline__ void cp_commit() {
    asm volatile("cp.async.commit_group;" ::: "memory");
}
template<int N>
__device__ __forceinline__ void cp_wait() {
    asm volatile("cp.async.wait_group %0;" :: "n"(N) : "memory");
}

// ---------------------------------------------------------------------------
// f32 -> f16 conversion, 4x batched grid-stride (MLP=4 independent loads).
// z selects {query,key,value,Wq,Wo}.
// ---------------------------------------------------------------------------
__global__ void cvt_kernel(const float* __restrict__ q,
                           const float* __restrict__ k,
                           const float* __restrict__ v,
                           const float* __restrict__ wq,
                           const float* __restrict__ wo)
{
    const int z = blockIdx.z;
    const float* src; __half* dst; int nf4;
    if      (z == 0) { src = q;  dst = g_xq; nf4 = MROWS * DM / 4; }
    else if (z == 1) { src = k;  dst = g_xk; nf4 = MROWS * DM / 4; }
    else if (z == 2) { src = v;  dst = g_xv; nf4 = MROWS * DM / 4; }
    else if (z == 3) { src = wq; dst = g_wq; nf4 = DM * DM / 4; }
    else             { src = wo; dst = g_wo; nf4 = DM * DM / 4; }

    const int stride = gridDim.x * blockDim.x;
    int i = blockIdx.x * blockDim.x + threadIdx.x;
    const float4* s4 = (const float4*)src;
    uint2* d2 = (uint2*)dst;

    for (; i + 3 * stride < nf4; i += 4 * stride) {
        float4 a = s4[i];
        float4 b = s4[i + stride];
        float4 c = s4[i + 2 * stride];
        float4 d = s4[i + 3 * stride];
        d2[i]              = cvt_f4h(a);
        d2[i + stride]     = cvt_f4h(b);
        d2[i + 2 * stride] = cvt_f4h(c);
        d2[i + 3 * stride] = cvt_f4h(d);
    }
    for (; i < nf4; i += stride)
        d2[i] = cvt_f4h(s4[i]);
}

// ---------------------------------------------------------------------------
// Unified big-tile fp16 GEMM: CTA 128x256, warp tile 64x64 (2m x 4n warps),
// 5-stage cp.async ring, distance 3, wait<1>, bar every 2 iters. 1 CTA/SM.
// A smem [128][40] halfs, B smem [32][264] halfs.
// MODE 0 (qkv): A = g_x{q,k,v} (z), W = g_wq; -> head layout (__half);
//               q (z==0) output scaled by log2(e)/sqrt(SEQ).
// MODE 1 (out): A = g_ctx, W = g_wo; -> f32 out + bias. Grid 128 = 1 wave.
// ---------------------------------------------------------------------------
#define QA_STR 40
#define QB_STR 264
#define QA_HALFS (128 * QA_STR)            // 5120
#define QB_HALFS (32 * QB_STR)             // 8448
#define Q_STAGE  (QA_HALFS + QB_HALFS)     // 13568 halfs
#define QKV_SMEM (5 * Q_STAGE * 2)         // 135680 bytes

__device__ __forceinline__ void big_stage(const __half* __restrict__ A,
                                          const __half* __restrict__ W,
                                          unsigned smBase, int buf, int kt,
                                          int tid)
{
    const unsigned aB = smBase + (unsigned)buf * (Q_STAGE * 2);
    const unsigned bB = aB + QA_HALFS * 2;
#pragma unroll
    for (int l = 0; l < 2; l++) {          // A: 128 rows x 32 halfs = 512 chunks
        int c = tid + l * 256;
        int row = c >> 2, c16 = c & 3;
        cp16(aB + (row * QA_STR + c16 * 8) * 2,
             A + (size_t)row * DM + kt + c16 * 8);
    }
#pragma unroll
    for (int l = 0; l < 4; l++) {          // B: 32 rows x 256 halfs = 1024 chunks
        int c = tid + l * 256;
        int row = c >> 5, c16 = c & 31;
        cp16(bB + (row * QB_STR + c16 * 8) * 2,
             W + (size_t)(kt + row) * DM + c16 * 8);
    }
}

template<int MODE>
__global__ __launch_bounds__(256, 1)
void gemm_big(const float* __restrict__ bias, float* __restrict__ Cout)
{
    extern __shared__ __half smh[];
    const unsigned smBase = (unsigned)__cvta_generic_to_shared(smh);

    const int tid  = threadIdx.x;
    const int warp = tid >> 5, lane = tid & 31;
    const int wm = warp >> 2, wn = warp & 3;
    const int grp = lane >> 2, qi = lane & 3;

    const int z = (MODE == 0) ? blockIdx.z : 0;
    const int gm0 = blockIdx.y * 128;
    const int gn0 = blockIdx.x * 256;

    const __half* __restrict__ A =
        ((MODE == 1) ? g_ctx : (z == 0 ? g_xq : (z == 1 ? g_xk : g_xv)))
        + (size_t)gm0 * DM;
    const __half* __restrict__ W =
        ((MODE == 0) ? g_wq : g_wo) + gn0;

    const unsigned aOff =
        (((wm * 64 + (lane & 7) + ((lane >> 3) & 1) * 8) * QA_STR)
         + (lane >> 4) * 8) * 2;
    const unsigned bOff = QA_HALFS * 2 +
        ((((lane >> 3) * 8 + (lane & 7)) * QB_STR) + wn * 64) * 2;

    float d[4][8][4];
#pragma unroll
    for (int mi = 0; mi < 4; mi++)
#pragma unroll
        for (int ni = 0; ni < 8; ni++)
#pragma unroll
            for (int r = 0; r < 4; r++) d[mi][ni][r] = 0.f;

    // prologue: stages 0, 1, 2
    big_stage(A, W, smBase, 0, 0,  tid); cp_commit();
    big_stage(A, W, smBase, 1, 32, tid); cp_commit();
    big_stage(A, W, smBase, 2, 64, tid); cp_commit();
    cp_wait<1>();
    __syncthreads();

    for (int it = 0; it < 32; it++) {
        const int buf = it % 5;
        if (it < 29)
            big_stage(A, W, smBase, (it + 3) % 5, (it + 3) * 32, tid);
        cp_commit();

        const unsigned sB = smBase + (unsigned)buf * (Q_STAGE * 2);
        unsigned bf[8][4];
#pragma unroll
        for (int ni = 0; ni < 8; ni++)
            ldsm_x4t(bf[ni], sB + bOff + ni * 16);
#pragma unroll
        for (int kp = 0; kp < 2; kp++) {
            unsigned af[4][4];
#pragma unroll
            for (int mi = 0; mi < 4; mi++)
                ldsm_x4(af[mi], sB + aOff + mi * 16 * (QA_STR * 2) + kp * 32);
#pragma unroll
            for (int mi = 0; mi < 4; mi++)
#pragma unroll
                for (int ni = 0; ni < 8; ni++)
                    mma_f16(d[mi][ni], af[mi], bf[ni][kp * 2], bf[ni][kp * 2 + 1]);
        }

        cp_wait<1>();
        if (it & 1) __syncthreads();
    }

    // ---- epilogue
    const float qsc = (MODE == 0 && z == 0)
                      ? 1.4426950408889634f * rsqrtf((float)SEQ) : 1.0f;
#pragma unroll
    for (int ni = 0; ni < 8; ni++) {
        const int gcol = gn0 + wn * 64 + ni * 8 + qi * 2;
        const float b0 = bias[gcol], b1 = bias[gcol + 1];
#pragma unroll
        for (int mi = 0; mi < 4; mi++) {
            const int gr = gm0 + wm * 64 + mi * 16 + grp;
#pragma unroll
            for (int hh = 0; hh < 2; hh++) {
                const int gm = gr + hh * 8;
                if (MODE == 0) {
                    const float v0 = (d[mi][ni][hh * 2 + 0] + b0) * qsc;
                    const float v1 = (d[mi][ni][hh * 2 + 1] + b1) * qsc;
                    __half* out = (z == 0) ? g_q : (z == 1) ? g_k : g_v;
                    const int h = gcol >> 6, dd = gcol & 63;
                    const int b = gm >> 11, s = gm & (SEQ - 1);
                    *(unsigned*)&out[(((size_t)h * BATCH + b) * SEQ + s) * DKH + dd]
                        = pack_h2(v0, v1);
                } else {
                    *(float2*)&Cout[(size_t)gm * DM + gcol] =
                        make_float2(d[mi][ni][hh * 2 + 0] + b0,
                                    d[mi][ni][hh * 2 + 1] + b1);
                }
            }
        }
    }
}

// ---------------------------------------------------------------------------
// fp16 flash attention per (h,b) (R14/R15-proven): BQ=256, 8 warps x 32
// q-rows; Q in regs; K/V 5-stage cp.async ring, bar every 2 iters; exp2f.
// ---------------------------------------------------------------------------
#define KV_STR 72
#define KV_HALFS (64 * KV_STR)              // 4608 halfs (one K or V tile)
#define AT_STAGE (2 * KV_HALFS)             // 9216 halfs per stage
#define ATT_SMEM_BYTES (5 * AT_STAGE * 2)   // 92160 bytes

__device__ __forceinline__ void attn_stage(const __half* __restrict__ K,
                                           const __half* __restrict__ V,
                                           unsigned smBase, int buf,
                                           size_t kb, int tid)
{
    const unsigned base = smBase + (unsigned)buf * (AT_STAGE * 2);
#pragma unroll
    for (int l = 0; l < 2; l++) {
        int c = tid + l * 256;
        int row = c >> 3, c16 = c & 7;
        cp16(base + (row * KV_STR + c16 * 8) * 2,
             K + (kb + row) * DKH + c16 * 8);
    }
#pragma unroll
    for (int l = 0; l < 2; l++) {
        int c = tid + l * 256;
        int row = c >> 3, c16 = c & 7;
        cp16(base + KV_HALFS * 2 + (row * KV_STR + c16 * 8) * 2,
             V + (kb + row) * DKH + c16 * 8);
    }
}

__global__ __launch_bounds__(256)
void attn_kernel()
{
    extern __shared__ __half smh[];
    const unsigned smBase = (unsigned)__cvta_generic_to_shared(smh);

    const int tid  = threadIdx.x;
    const int warp = tid >> 5, lane = tid & 31;
    const int grp  = lane >> 2, qi = lane & 3;
    const int hb   = blockIdx.y;
    const int q0   = blockIdx.x * 256;

    const __half* __restrict__ Q = g_q + (size_t)hb * SEQ * DKH;
    const __half* __restrict__ K = g_k + (size_t)hb * SEQ * DKH;
    const __half* __restrict__ V = g_v + (size_t)hb * SEQ * DKH;

    const int row0 = warp * 32;
    const int rowL = tid >> 3, c8 = tid & 7;

    // ---- stage Q into (aliased) smem, ldmatrix to regs, then release smem
#pragma unroll
    for (int l = 0; l < 8; l++) {
        const int r = rowL + l * 32;
        uint4 v = *(const uint4*)&Q[(size_t)(q0 + r) * DKH + c8 * 8];
        *(uint4*)&smh[r * KV_STR + c8 * 8] = v;
    }
    __syncthreads();

    unsigned qf[2][4][4];
    {
        const unsigned qLane = smBase +
            (((row0 + (lane & 7) + ((lane >> 3) & 1) * 8) * KV_STR)
             + (lane >> 4) * 8) * 2;
#pragma unroll
        for (int m = 0; m < 2; m++)
#pragma unroll
            for (int kp = 0; kp < 4; kp++)
                ldsm_x4(qf[m][kp], qLane + m * 16 * (KV_STR * 2) + kp * 32);
    }
    __syncthreads();

    const unsigned kOff = (((lane & 7) * KV_STR) + (lane >> 3) * 8) * 2;
    const unsigned vOff = KV_HALFS * 2 +
        (((lane >> 3) * 8 + (lane & 7)) * KV_STR) * 2;

    float o[2][8][4];
    float rs[2][2];
#pragma unroll
    for (int m = 0; m < 2; m++) {
        rs[m][0] = 0.f; rs[m][1] = 0.f;
#pragma unroll
        for (int ni = 0; ni < 8; ni++)
#pragma unroll
            for (int r = 0; r < 4; r++) o[m][ni][r] = 0.f;
    }

    attn_stage(K, V, smBase, 0, 0,   tid); cp_commit();
    attn_stage(K, V, smBase, 1, 64,  tid); cp_commit();
    attn_stage(K, V, smBase, 2, 128, tid); cp_commit();
    cp_wait<1>();
    __syncthreads();

    for (int it = 0; it < 32; it++) {
        const int buf = it % 5;
        if (it < 29)
            attn_stage(K, V, smBase, (it + 3) % 5, (size_t)(it + 3) * 64, tid);
        cp_commit();

        const unsigned sB = smBase + (unsigned)buf * (AT_STAGE * 2);

        float s[2][8][4];
#pragma unroll
        for (int m = 0; m < 2; m++)
#pragma unroll
            for (int ni = 0; ni < 8; ni++)
#pragma unroll
                for (int r = 0; r < 4; r++) s[m][ni][r] = 0.f;

#pragma unroll
        for (int kq = 0; kq < 2; kq++) {
#pragma unroll
            for (int ni = 0; ni < 8; ni++) {
                unsigned kf[4];
                ldsm_x4(kf, sB + kOff + (ni * 8 * KV_STR) * 2 + kq * 64);
#pragma unroll
                for (int m = 0; m < 2; m++) {
                    mma_f16(s[m][ni], qf[m][2 * kq],     kf[0], kf[1]);
                    mma_f16(s[m][ni], qf[m][2 * kq + 1], kf[2], kf[3]);
                }
            }
        }

        unsigned ps[2][4][4];
#pragma unroll
        for (int m = 0; m < 2; m++)
#pragma unroll
            for (int tp = 0; tp < 4; tp++) {
                const float* sa = s[m][2 * tp];
                const float* sb = s[m][2 * tp + 1];
                float e0 = exp2f(sa[0]), e1 = exp2f(sa[1]);
                float e2 = exp2f(sa[2]), e3 = exp2f(sa[3]);
                float f0 = exp2f(sb[0]), f1 = exp2f(sb[1]);
                float f2 = exp2f(sb[2]), f3 = exp2f(sb[3]);
                rs[m][0] += (e0 + e1) + (f0 + f1);
                rs[m][1] += (e2 + e3) + (f2 + f3);
                ps[m][tp][0] = pack_h2(e0, e1);
                ps[m][tp][1] = pack_h2(e2, e3);
                ps[m][tp][2] = pack_h2(f0, f1);
                ps[m][tp][3] = pack_h2(f2, f3);
            }

#pragma unroll
        for (int tq = 0; tq < 2; tq++) {
#pragma unroll
            for (int ni = 0; ni < 8; ni++) {
                unsigned vf[4];
                ldsm_x4t(vf, sB + vOff + (tq * 32 * KV_STR) * 2 + ni * 16);
#pragma unroll
                for (int m = 0; m < 2; m++) {
                    mma_f16(o[m][ni], ps[m][2 * tq],     vf[0], vf[1]);
                    mma_f16(o[m][ni], ps[m][2 * tq + 1], vf[2], vf[3]);
                }
            }
        }

        cp_wait<1>();
        if (it & 1) __syncthreads();
    }

#pragma unroll
    for (int m = 0; m < 2; m++)
#pragma unroll
        for (int j = 0; j < 2; j++) {
            float r = rs[m][j];
            r += __shfl_xor_sync(0xffffffffu, r, 1);
            r += __shfl_xor_sync(0xffffffffu, r, 2);
            rs[m][j] = 1.f / r;
        }

    const int h = hb >> 1, b = hb & 1;
#pragma unroll
    for (int m = 0; m < 2; m++) {
        const int sr0 = q0 + row0 + m * 16 + grp;
#pragma unroll
        for (int ni = 0; ni < 8; ni++) {
            const int col = h * DKH + ni * 8 + qi * 2;
            *(unsigned*)&g_ctx[((size_t)(b * SEQ + sr0)) * DM + col] =
                pack_h2(o[m][ni][0] * rs[m][0], o[m][ni][1] * rs[m][0]);
            *(unsigned*)&g_ctx[((size_t)(b * SEQ + sr0 + 8)) * DM + col] =
                pack_h2(o[m][ni][2] * rs[m][1], o[m][ni][3] * rs[m][1]);
        }
    }
}

// ---------------------------------------------------------------------------
extern "C" void kernel_launch(void* const* d_in, const int* in_sizes, int n_in,
                              void* d_out, int out_size)
{
    (void)in_sizes; (void)n_in; (void)out_size;
    const float* query = (const float*)d_in[0];
    const float* key   = (const float*)d_in[1];
    const float* value = (const float*)d_in[2];
    const float* Wq    = (const float*)d_in[3];
    const float* bq    = (const float*)d_in[4];
    const float* Wo    = (const float*)d_in[5];
    const float* bo    = (const float*)d_in[6];
    float* out = (float*)d_out;

    cudaFuncSetAttribute(gemm_big<0>,
                         cudaFuncAttributeMaxDynamicSharedMemorySize, QKV_SMEM);
    cudaFuncSetAttribute(gemm_big<1>,
                         cudaFuncAttributeMaxDynamicSharedMemorySize, QKV_SMEM);
    cudaFuncSetAttribute(attn_kernel,
                         cudaFuncAttributeMaxDynamicSharedMemorySize,
                         ATT_SMEM_BYTES);

    dim3 blk(256);
    cvt_kernel<<<dim3(1024, 1, 5), blk>>>(query, key, value, Wq, Wo);
    gemm_big<0><<<dim3(DM / 256, MROWS / 128, 3), blk, QKV_SMEM>>>(bq, nullptr);
    attn_kernel<<<dim3(SEQ / 256, HEADS * BATCH), blk, ATT_SMEM_BYTES>>>();
    gemm_big<1><<<dim3(DM / 256, MROWS / 128, 1), blk, QKV_SMEM>>>(bo, out);
}

// round 17
// speedup vs baseline: 1.2631x; 1.0673x over previous
#include <cuda_runtime.h>
#include <cuda_fp16.h>
#include <math.h>
#include <stdint.h>

#define DM     1024
#define HEADS  16
#define DKH    64
#define BATCH  2
#define SEQ    2048
#define MROWS  (BATCH*SEQ)   // 4096

// Scratch (device globals; allocation-free per harness rules)
__device__ __half g_q[HEADS*BATCH*SEQ*DKH];    // head-layout projections
__device__ __half g_k[HEADS*BATCH*SEQ*DKH];
__device__ __half g_v[HEADS*BATCH*SEQ*DKH];
__device__ __half g_ctx[(size_t)MROWS*DM];     // attention output (concat)
__device__ __half g_xq[(size_t)MROWS*DM];      // fp16 copies of inputs
__device__ __half g_xk[(size_t)MROWS*DM];
__device__ __half g_xv[(size_t)MROWS*DM];
__device__ __half g_wq[(size_t)DM*DM];         // fp16 weights
__device__ __half g_wo[(size_t)DM*DM];

// ---- helpers --------------------------------------------------------------
__device__ __forceinline__ unsigned pack_h2(float a, float b) {
    __half2 h = __floats2half2_rn(a, b);
    return *reinterpret_cast<unsigned*>(&h);
}
__device__ __forceinline__ unsigned h2exp2(unsigned x) {
    unsigned r;
    asm("ex2.approx.f16x2 %0, %1;" : "=r"(r) : "r"(x));
    return r;
}
__device__ __forceinline__ uint2 cvt_f4h(float4 v) {
    uint2 r; r.x = pack_h2(v.x, v.y); r.y = pack_h2(v.z, v.w); return r;
}
__device__ __forceinline__ void mma_f16(float d[4], const unsigned a[4],
                                        unsigned b0, unsigned b1) {
    asm("mma.sync.aligned.m16n8k16.row.col.f32.f16.f16.f32 "
        "{%0,%1,%2,%3}, {%4,%5,%6,%7}, {%8,%9}, {%0,%1,%2,%3};"
        : "+f"(d[0]), "+f"(d[1]), "+f"(d[2]), "+f"(d[3])
        : "r"(a[0]), "r"(a[1]), "r"(a[2]), "r"(a[3]), "r"(b0), "r"(b1));
}
__device__ __forceinline__ void ldsm_x4(unsigned r[4], unsigned saddr) {
    asm volatile("ldmatrix.sync.aligned.m8n8.x4.shared.b16 {%0,%1,%2,%3}, [%4];"
                 : "=r"(r[0]), "=r"(r[1]), "=r"(r[2]), "=r"(r[3])
                 : "r"(saddr));
}
__device__ __forceinline__ void ldsm_x4t(unsigned r[4], unsigned saddr) {
    asm volatile("ldmatrix.sync.aligned.m8n8.x4.trans.shared.b16 {%0,%1,%2,%3}, [%4];"
                 : "=r"(r[0]), "=r"(r[1]), "=r"(r[2]), "=r"(r[3])
                 : "r"(saddr));
}
__device__ __forceinline__ void cp16(unsigned dst, const void* src) {
    asm volatile("cp.async.cg.shared.global [%0], [%1], 16;"
                 :: "r"(dst), "l"(src));
}
__device__ __forceinline__ void cp_commit() {
    asm volatile("cp.async.commit_group;" ::: "memory");
}
template<int N>
__device__ __forceinline__ void cp_wait() {
    asm volatile("cp.async.wait_group %0;" :: "n"(N) : "memory");
}

// ---------------------------------------------------------------------------
// f32 -> f16 conversion, 4x batched grid-stride.
// ---------------------------------------------------------------------------
__global__ void cvt_kernel(const float* __restrict__ q,
                           const float* __restrict__ k,
                           const float* __restrict__ v,
                           const float* __restrict__ wq,
                           const float* __restrict__ wo)
{
    const int z = blockIdx.z;
    const float* src; __half* dst; int nf4;
    if      (z == 0) { src = q;  dst = g_xq; nf4 = MROWS * DM / 4; }
    else if (z == 1) { src = k;  dst = g_xk; nf4 = MROWS * DM / 4; }
    else if (z == 2) { src = v;  dst = g_xv; nf4 = MROWS * DM / 4; }
    else if (z == 3) { src = wq; dst = g_wq; nf4 = DM * DM / 4; }
    else             { src = wo; dst = g_wo; nf4 = DM * DM / 4; }

    const int stride = gridDim.x * blockDim.x;
    int i = blockIdx.x * blockDim.x + threadIdx.x;
    const float4* s4 = (const float4*)src;
    uint2* d2 = (uint2*)dst;

    for (; i + 3 * stride < nf4; i += 4 * stride) {
        float4 a = s4[i];
        float4 b = s4[i + stride];
        float4 c = s4[i + 2 * stride];
        float4 d = s4[i + 3 * stride];
        d2[i]              = cvt_f4h(a);
        d2[i + stride]     = cvt_f4h(b);
        d2[i + 2 * stride] = cvt_f4h(c);
        d2[i + 3 * stride] = cvt_f4h(d);
    }
    for (; i < nf4; i += stride)
        d2[i] = cvt_f4h(s4[i]);
}

// ---------------------------------------------------------------------------
// Unified big-tile fp16 GEMM (R16-proven): CTA 128x256, warp tile 64x64,
// 5-stage cp.async ring, distance 3, wait<1>, bar every 2 iters. 1 CTA/SM.
// ---------------------------------------------------------------------------
#define QA_STR 40
#define QB_STR 264
#define QA_HALFS (128 * QA_STR)            // 5120
#define QB_HALFS (32 * QB_STR)             // 8448
#define Q_STAGE  (QA_HALFS + QB_HALFS)     // 13568 halfs
#define QKV_SMEM (5 * Q_STAGE * 2)         // 135680 bytes

__device__ __forceinline__ void big_stage(const __half* __restrict__ A,
                                          const __half* __restrict__ W,
                                          unsigned smBase, int buf, int kt,
                                          int tid)
{
    const unsigned aB = smBase + (unsigned)buf * (Q_STAGE * 2);
    const unsigned bB = aB + QA_HALFS * 2;
#pragma unroll
    for (int l = 0; l < 2; l++) {
        int c = tid + l * 256;
        int row = c >> 2, c16 = c & 3;
        cp16(aB + (row * QA_STR + c16 * 8) * 2,
             A + (size_t)row * DM + kt + c16 * 8);
    }
#pragma unroll
    for (int l = 0; l < 4; l++) {
        int c = tid + l * 256;
        int row = c >> 5, c16 = c & 31;
        cp16(bB + (row * QB_STR + c16 * 8) * 2,
             W + (size_t)(kt + row) * DM + c16 * 8);
    }
}

template<int MODE>
__global__ __launch_bounds__(256, 1)
void gemm_big(const float* __restrict__ bias, float* __restrict__ Cout)
{
    extern __shared__ __half smh[];
    const unsigned smBase = (unsigned)__cvta_generic_to_shared(smh);

    const int tid  = threadIdx.x;
    const int warp = tid >> 5, lane = tid & 31;
    const int wm = warp >> 2, wn = warp & 3;
    const int grp = lane >> 2, qi = lane & 3;

    const int z = (MODE == 0) ? blockIdx.z : 0;
    const int gm0 = blockIdx.y * 128;
    const int gn0 = blockIdx.x * 256;

    const __half* __restrict__ A =
        ((MODE == 1) ? g_ctx : (z == 0 ? g_xq : (z == 1 ? g_xk : g_xv)))
        + (size_t)gm0 * DM;
    const __half* __restrict__ W =
        ((MODE == 0) ? g_wq : g_wo) + gn0;

    const unsigned aOff =
        (((wm * 64 + (lane & 7) + ((lane >> 3) & 1) * 8) * QA_STR)
         + (lane >> 4) * 8) * 2;
    const unsigned bOff = QA_HALFS * 2 +
        ((((lane >> 3) * 8 + (lane & 7)) * QB_STR) + wn * 64) * 2;

    float d[4][8][4];
#pragma unroll
    for (int mi = 0; mi < 4; mi++)
#pragma unroll
        for (int ni = 0; ni < 8; ni++)
#pragma unroll
            for (int r = 0; r < 4; r++) d[mi][ni][r] = 0.f;

    big_stage(A, W, smBase, 0, 0,  tid); cp_commit();
    big_stage(A, W, smBase, 1, 32, tid); cp_commit();
    big_stage(A, W, smBase, 2, 64, tid); cp_commit();
    cp_wait<1>();
    __syncthreads();

    for (int it = 0; it < 32; it++) {
        const int buf = it % 5;
        if (it < 29)
            big_stage(A, W, smBase, (it + 3) % 5, (it + 3) * 32, tid);
        cp_commit();

        const unsigned sB = smBase + (unsigned)buf * (Q_STAGE * 2);
        unsigned bf[8][4];
#pragma unroll
        for (int ni = 0; ni < 8; ni++)
            ldsm_x4t(bf[ni], sB + bOff + ni * 16);
#pragma unroll
        for (int kp = 0; kp < 2; kp++) {
            unsigned af[4][4];
#pragma unroll
            for (int mi = 0; mi < 4; mi++)
                ldsm_x4(af[mi], sB + aOff + mi * 16 * (QA_STR * 2) + kp * 32);
#pragma unroll
            for (int mi = 0; mi < 4; mi++)
#pragma unroll
                for (int ni = 0; ni < 8; ni++)
                    mma_f16(d[mi][ni], af[mi], bf[ni][kp * 2], bf[ni][kp * 2 + 1]);
        }

        cp_wait<1>();
        if (it & 1) __syncthreads();
    }

    const float qsc = (MODE == 0 && z == 0)
                      ? 1.4426950408889634f * rsqrtf((float)SEQ) : 1.0f;
#pragma unroll
    for (int ni = 0; ni < 8; ni++) {
        const int gcol = gn0 + wn * 64 + ni * 8 + qi * 2;
        const float b0 = bias[gcol], b1 = bias[gcol + 1];
#pragma unroll
        for (int mi = 0; mi < 4; mi++) {
            const int gr = gm0 + wm * 64 + mi * 16 + grp;
#pragma unroll
            for (int hh = 0; hh < 2; hh++) {
                const int gm = gr + hh * 8;
                if (MODE == 0) {
                    const float v0 = (d[mi][ni][hh * 2 + 0] + b0) * qsc;
                    const float v1 = (d[mi][ni][hh * 2 + 1] + b1) * qsc;
                    __half* out = (z == 0) ? g_q : (z == 1) ? g_k : g_v;
                    const int h = gcol >> 6, dd = gcol & 63;
                    const int b = gm >> 11, s = gm & (SEQ - 1);
                    *(unsigned*)&out[(((size_t)h * BATCH + b) * SEQ + s) * DKH + dd]
                        = pack_h2(v0, v1);
                } else {
                    *(float2*)&Cout[(size_t)gm * DM + gcol] =
                        make_float2(d[mi][ni][hh * 2 + 0] + b0,
                                    d[mi][ni][hh * 2 + 1] + b1);
                }
            }
        }
    }
}

// ---------------------------------------------------------------------------
// fp16 flash attention per (h,b): BQ=256, 8 warps x 32 q-rows; Q in regs;
// K/V 5-stage cp.async ring, bar every 2 iters.
// NEW: softmax via ex2.approx.f16x2 (half the MUFU ops) and rowsum computed
// ON THE TENSOR CORE (P @ ones with constant B-fragment) -> no FADD chain,
// no final shfl reduction.
// ---------------------------------------------------------------------------
#define KV_STR 72
#define KV_HALFS (64 * KV_STR)              // 4608 halfs (one K or V tile)
#define AT_STAGE (2 * KV_HALFS)             // 9216 halfs per stage
#define ATT_SMEM_BYTES (5 * AT_STAGE * 2)   // 92160 bytes
#define ONE2 0x3C003C00u                    // half2(1.0, 1.0)

__device__ __forceinline__ void attn_stage(const __half* __restrict__ K,
                                           const __half* __restrict__ V,
                                           unsigned smBase, int buf,
                                           size_t kb, int tid)
{
    const unsigned base = smBase + (unsigned)buf * (AT_STAGE * 2);
#pragma unroll
    for (int l = 0; l < 2; l++) {
        int c = tid + l * 256;
        int row = c >> 3, c16 = c & 7;
        cp16(base + (row * KV_STR + c16 * 8) * 2,
             K + (kb + row) * DKH + c16 * 8);
    }
#pragma unroll
    for (int l = 0; l < 2; l++) {
        int c = tid + l * 256;
        int row = c >> 3, c16 = c & 7;
        cp16(base + KV_HALFS * 2 + (row * KV_STR + c16 * 8) * 2,
             V + (kb + row) * DKH + c16 * 8);
    }
}

__global__ __launch_bounds__(256)
void attn_kernel()
{
    extern __shared__ __half smh[];
    const unsigned smBase = (unsigned)__cvta_generic_to_shared(smh);

    const int tid  = threadIdx.x;
    const int warp = tid >> 5, lane = tid & 31;
    const int grp  = lane >> 2, qi = lane & 3;
    const int hb   = blockIdx.y;
    const int q0   = blockIdx.x * 256;

    const __half* __restrict__ Q = g_q + (size_t)hb * SEQ * DKH;
    const __half* __restrict__ K = g_k + (size_t)hb * SEQ * DKH;
    const __half* __restrict__ V = g_v + (size_t)hb * SEQ * DKH;

    const int row0 = warp * 32;
    const int rowL = tid >> 3, c8 = tid & 7;

    // ---- stage Q into (aliased) smem, ldmatrix to regs, then release smem
#pragma unroll
    for (int l = 0; l < 8; l++) {
        const int r = rowL + l * 32;
        uint4 v = *(const uint4*)&Q[(size_t)(q0 + r) * DKH + c8 * 8];
        *(uint4*)&smh[r * KV_STR + c8 * 8] = v;
    }
    __syncthreads();

    unsigned qf[2][4][4];
    {
        const unsigned qLane = smBase +
            (((row0 + (lane & 7) + ((lane >> 3) & 1) * 8) * KV_STR)
             + (lane >> 4) * 8) * 2;
#pragma unroll
        for (int m = 0; m < 2; m++)
#pragma unroll
            for (int kp = 0; kp < 4; kp++)
                ldsm_x4(qf[m][kp], qLane + m * 16 * (KV_STR * 2) + kp * 32);
    }
    __syncthreads();

    const unsigned kOff = (((lane & 7) * KV_STR) + (lane >> 3) * 8) * 2;
    const unsigned vOff = KV_HALFS * 2 +
        (((lane >> 3) * 8 + (lane & 7)) * KV_STR) * 2;

    float o[2][8][4];
    float rsacc[2][4];      // tensor-core rowsum accumulators (P @ ones)
#pragma unroll
    for (int m = 0; m < 2; m++) {
#pragma unroll
        for (int r = 0; r < 4; r++) rsacc[m][r] = 0.f;
#pragma unroll
        for (int ni = 0; ni < 8; ni++)
#pragma unroll
            for (int r = 0; r < 4; r++) o[m][ni][r] = 0.f;
    }

    attn_stage(K, V, smBase, 0, 0,   tid); cp_commit();
    attn_stage(K, V, smBase, 1, 64,  tid); cp_commit();
    attn_stage(K, V, smBase, 2, 128, tid); cp_commit();
    cp_wait<1>();
    __syncthreads();

    for (int it = 0; it < 32; it++) {
        const int buf = it % 5;
        if (it < 29)
            attn_stage(K, V, smBase, (it + 3) % 5, (size_t)(it + 3) * 64, tid);
        cp_commit();

        const unsigned sB = smBase + (unsigned)buf * (AT_STAGE * 2);

        // ---- S = Q @ K^T (pre-scaled by log2e/sqrt(SEQ))
        float s[2][8][4];
#pragma unroll
        for (int m = 0; m < 2; m++)
#pragma unroll
            for (int ni = 0; ni < 8; ni++)
#pragma unroll
                for (int r = 0; r < 4; r++) s[m][ni][r] = 0.f;

#pragma unroll
        for (int kq = 0; kq < 2; kq++) {
#pragma unroll
            for (int ni = 0; ni < 8; ni++) {
                unsigned kf[4];
                ldsm_x4(kf, sB + kOff + (ni * 8 * KV_STR) * 2 + kq * 64);
#pragma unroll
                for (int m = 0; m < 2; m++) {
                    mma_f16(s[m][ni], qf[m][2 * kq],     kf[0], kf[1]);
                    mma_f16(s[m][ni], qf[m][2 * kq + 1], kf[2], kf[3]);
                }
            }
        }

        // ---- P = exp2(S) entirely in half2 (ex2.approx.f16x2)
        unsigned ps[2][4][4];
#pragma unroll
        for (int m = 0; m < 2; m++)
#pragma unroll
            for (int tp = 0; tp < 4; tp++) {
                const float* sa = s[m][2 * tp];
                const float* sb = s[m][2 * tp + 1];
                ps[m][tp][0] = h2exp2(pack_h2(sa[0], sa[1]));
                ps[m][tp][1] = h2exp2(pack_h2(sa[2], sa[3]));
                ps[m][tp][2] = h2exp2(pack_h2(sb[0], sb[1]));
                ps[m][tp][3] = h2exp2(pack_h2(sb[2], sb[3]));
            }

        // ---- O += P @ V ; rowsum += P @ ones (constant B-fragment)
#pragma unroll
        for (int tq = 0; tq < 2; tq++) {
#pragma unroll
            for (int ni = 0; ni < 8; ni++) {
                unsigned vf[4];
                ldsm_x4t(vf, sB + vOff + (tq * 32 * KV_STR) * 2 + ni * 16);
#pragma unroll
                for (int m = 0; m < 2; m++) {
                    mma_f16(o[m][ni], ps[m][2 * tq],     vf[0], vf[1]);
                    mma_f16(o[m][ni], ps[m][2 * tq + 1], vf[2], vf[3]);
                }
            }
#pragma unroll
            for (int m = 0; m < 2; m++) {
                mma_f16(rsacc[m], ps[m][2 * tq],     ONE2, ONE2);
                mma_f16(rsacc[m], ps[m][2 * tq + 1], ONE2, ONE2);
            }
        }

        cp_wait<1>();
        if (it & 1) __syncthreads();
    }

    // rowsums: all columns equal; rows grp -> d[0], grp+8 -> d[2]
    const int h = hb >> 1, b = hb & 1;
#pragma unroll
    for (int m = 0; m < 2; m++) {
        const float rinv0 = 1.f / rsacc[m][0];
        const float rinv1 = 1.f / rsacc[m][2];
        const int sr0 = q0 + row0 + m * 16 + grp;
#pragma unroll
        for (int ni = 0; ni < 8; ni++) {
            const int col = h * DKH + ni * 8 + qi * 2;
            *(unsigned*)&g_ctx[((size_t)(b * SEQ + sr0)) * DM + col] =
                pack_h2(o[m][ni][0] * rinv0, o[m][ni][1] * rinv0);
            *(unsigned*)&g_ctx[((size_t)(b * SEQ + sr0 + 8)) * DM + col] =
                pack_h2(o[m][ni][2] * rinv1, o[m][ni][3] * rinv1);
        }
    }
}

// ---------------------------------------------------------------------------
extern "C" void kernel_launch(void* const* d_in, const int* in_sizes, int n_in,
                              void* d_out, int out_size)
{
    (void)in_sizes; (void)n_in; (void)out_size;
    const float* query = (const float*)d_in[0];
    const float* key   = (const float*)d_in[1];
    const float* value = (const float*)d_in[2];
    const float* Wq    = (const float*)d_in[3];
    const float* bq    = (const float*)d_in[4];
    const float* Wo    = (const float*)d_in[5];
    const float* bo    = (const float*)d_in[6];
    float* out = (float*)d_out;

    cudaFuncSetAttribute(gemm_big<0>,
                         cudaFuncAttributeMaxDynamicSharedMemorySize, QKV_SMEM);
    cudaFuncSetAttribute(gemm_big<1>,
                         cudaFuncAttributeMaxDynamicSharedMemorySize, QKV_SMEM);
    cudaFuncSetAttribute(attn_kernel,
                         cudaFuncAttributeMaxDynamicSharedMemorySize,
                         ATT_SMEM_BYTES);

    dim3 blk(256);
    cvt_kernel<<<dim3(1024, 1, 5), blk>>>(query, key, value, Wq, Wo);
    gemm_big<0><<<dim3(DM / 256, MROWS / 128, 3), blk, QKV_SMEM>>>(bq, nullptr);
    attn_kernel<<<dim3(SEQ / 256, HEADS * BATCH), blk, ATT_SMEM_BYTES>>>();
    gemm_big<1><<<dim3(DM / 256, MROWS / 128, 1), blk, QKV_SMEM>>>(bo, out);
}